// round 4
// baseline (speedup 1.0000x reference)
#include <cuda_runtime.h>
#include <cuda_bf16.h>
#include <cstdint>

#define NTOK   8192
#define INFEAT 128
#define DHEAD  64
#define NHEADS 2
#define MASKW  (NTOK/32)   // 256 words per row

#define BM 64
#define BN 64
#define NTILES (NTOK/BN)   // 128

__device__ __align__(16) uint32_t      g_adjbits[NTOK * MASKW];              // 8 MB
__device__ __align__(16) __nv_bfloat16 g_q[NHEADS][NTOK][DHEAD];             // 2 MB
__device__ __align__(16) __nv_bfloat16 g_k[NHEADS][NTOK][DHEAD];             // 2 MB
__device__ __align__(16) __nv_bfloat16 g_v[NHEADS][NTOK][DHEAD];             // 2 MB

// ---------------------------------------------------------------------------
// Kernel 1: pack adjacency int32 -> bitmask
// ---------------------------------------------------------------------------
__global__ void __launch_bounds__(256) pack_adj_kernel(const int* __restrict__ adj)
{
    long long idx = (long long)blockIdx.x * 256 + threadIdx.x;
    int val = adj[idx] > 0;
    unsigned mask = __ballot_sync(0xffffffffu, val);
    if ((threadIdx.x & 31) == 0)
        g_adjbits[idx >> 5] = mask;
}

// ---------------------------------------------------------------------------
// Kernel 2: fused projections. out[n][f] = sum_k h[n][k]*W[f][k] + b[f]
// f in [0,512): 0-127 Q (pre-scaled by 1/8, bf16), 128-255 K (bf16),
// 256-383 V (bf16), 384-511 skip (fp32, straight into d_out).
// One block = 32 rows, blockDim = 512 (one thread per feature).
// ---------------------------------------------------------------------------
__global__ void __launch_bounds__(512) proj_kernel(
    const float* __restrict__ h,
    const float* __restrict__ Wq, const float* __restrict__ bq,
    const float* __restrict__ Wk, const float* __restrict__ bk,
    const float* __restrict__ Wv, const float* __restrict__ bv,
    const float* __restrict__ Ws, const float* __restrict__ bs,
    float* __restrict__ out)
{
    __shared__ float4 h_s[32][32];   // 32 rows x 128 floats
    int tid = threadIdx.x;
    int rowbase = blockIdx.x * 32;

    const float4* h4 = (const float4*)(h + (long long)rowbase * INFEAT);
    for (int i = tid; i < 32 * 32; i += 512)
        h_s[i >> 5][i & 31] = h4[i];
    __syncthreads();

    int f = tid;
    const float* W; const float* B; int kind, fo;
    if (f < 128)      { W = Wq; B = bq; kind = 0; fo = f; }
    else if (f < 256) { W = Wk; B = bk; kind = 1; fo = f - 128; }
    else if (f < 384) { W = Wv; B = bv; kind = 2; fo = f - 256; }
    else              { W = Ws; B = bs; kind = 3; fo = f - 384; }

    float acc[32];
    float bias = B[fo];
    #pragma unroll
    for (int r = 0; r < 32; r++) acc[r] = bias;

    const float4* Wrow = (const float4*)(W + fo * INFEAT);
    #pragma unroll
    for (int kt = 0; kt < 4; kt++) {
        float4 w[8];
        #pragma unroll
        for (int j = 0; j < 8; j++) w[j] = Wrow[kt * 8 + j];
        #pragma unroll
        for (int r = 0; r < 32; r++) {
            float a = acc[r];
            #pragma unroll
            for (int j = 0; j < 8; j++) {
                float4 hv = h_s[r][kt * 8 + j];
                a += hv.x * w[j].x;
                a += hv.y * w[j].y;
                a += hv.z * w[j].z;
                a += hv.w * w[j].w;
            }
            acc[r] = a;
        }
    }

    int head = fo >> 6, d = fo & 63;
    #pragma unroll
    for (int r = 0; r < 32; r++) {
        int n = rowbase + r;
        if (kind == 0)      g_q[head][n][d] = __float2bfloat16(acc[r] * 0.125f);
        else if (kind == 1) g_k[head][n][d] = __float2bfloat16(acc[r]);
        else if (kind == 2) g_v[head][n][d] = __float2bfloat16(acc[r]);
        else                out[(long long)n * 128 + fo] = acc[r];
    }
}

// ---------------------------------------------------------------------------
// Kernel 3: masked flash attention (no-max softmax), bf16 mma.sync
// ---------------------------------------------------------------------------
__device__ __forceinline__ uint32_t s2u(const void* p) {
    return (uint32_t)__cvta_generic_to_shared(p);
}

#define CP16(dst, src) asm volatile("cp.async.cg.shared.global [%0], [%1], 16;\n" :: "r"(dst), "l"(src) : "memory")
#define CP4(dst, src)  asm volatile("cp.async.ca.shared.global [%0], [%1], 4;\n"  :: "r"(dst), "l"(src) : "memory")
#define CP_COMMIT()    asm volatile("cp.async.commit_group;\n" ::: "memory")
#define CP_WAIT1()     asm volatile("cp.async.wait_group 1;\n" ::: "memory")
#define CP_WAIT0()     asm volatile("cp.async.wait_group 0;\n" ::: "memory")

__device__ __forceinline__ void ldsm4(uint32_t* d, uint32_t addr) {
    asm volatile("ldmatrix.sync.aligned.m8n8.x4.shared.b16 {%0,%1,%2,%3}, [%4];\n"
        : "=r"(d[0]), "=r"(d[1]), "=r"(d[2]), "=r"(d[3]) : "r"(addr));
}
__device__ __forceinline__ void ldsm4t(uint32_t* d, uint32_t addr) {
    asm volatile("ldmatrix.sync.aligned.m8n8.x4.trans.shared.b16 {%0,%1,%2,%3}, [%4];\n"
        : "=r"(d[0]), "=r"(d[1]), "=r"(d[2]), "=r"(d[3]) : "r"(addr));
}
__device__ __forceinline__ void mma16816(float* c, const uint32_t* a, const uint32_t* b) {
    asm volatile("mma.sync.aligned.m16n8k16.row.col.f32.bf16.bf16.f32 "
        "{%0,%1,%2,%3}, {%4,%5,%6,%7}, {%8,%9}, {%0,%1,%2,%3};\n"
        : "+f"(c[0]), "+f"(c[1]), "+f"(c[2]), "+f"(c[3])
        : "r"(a[0]), "r"(a[1]), "r"(a[2]), "r"(a[3]), "r"(b[0]), "r"(b[1]));
}

__global__ void __launch_bounds__(128, 2) attn_kernel(float* __restrict__ out)
{
    int mtile = blockIdx.x, head = blockIdx.y;
    int tid = threadIdx.x, warp = tid >> 5, lane = tid & 31;
    int g = lane >> 2, t4 = lane & 3;

    __shared__ __align__(16) __nv_bfloat16 q_s[BM * DHEAD];        // 8 KB, swizzled
    __shared__ __align__(16) __nv_bfloat16 k_s[2][BN * DHEAD];     // 16 KB
    __shared__ __align__(16) __nv_bfloat16 v_s[2][BN * DHEAD];     // 16 KB
    __shared__ uint32_t mask_s[2][BM * 2];                          // 1 KB

    // ---- stage Q tile (LDG -> STS, swizzled: 16B chunk ^ (row&7)) ----
    {
        const uint4* qg = (const uint4*)&g_q[head][mtile * BM][0];
        uint4* q4 = (uint4*)q_s;
        for (int i = tid; i < 512; i += 128) {
            int r = i >> 3, c = i & 7;
            q4[r * 8 + (c ^ (r & 7))] = qg[i];
        }
    }
    __syncthreads();

    // ---- load Q a-frags into registers (resident whole kernel) ----
    uint32_t qf[4][4];
    {
        char* qb = (char*)q_s;
        #pragma unroll
        for (int kt = 0; kt < 4; kt++) {
            int r = warp * 16 + (lane & 15);
            int kc = kt * 2 + (lane >> 4);
            uint32_t addr = s2u(qb + r * 128 + ((kc ^ (r & 7)) << 4));
            ldsm4(qf[kt], addr);
        }
    }

    float o[8][4];
    #pragma unroll
    for (int j = 0; j < 8; j++)
        { o[j][0] = 0.f; o[j][1] = 0.f; o[j][2] = 0.f; o[j][3] = 0.f; }
    float lsum0 = 0.f, lsum1 = 0.f;

    const int rA = warp * 16 + g, rB = rA + 8;

    // ---- prefetch tile 0 ----
    {
        const uint4* kg = (const uint4*)&g_k[head][0][0];
        const uint4* vg = (const uint4*)&g_v[head][0][0];
        uint4* ks4 = (uint4*)k_s[0];
        uint4* vs4 = (uint4*)v_s[0];
        for (int i = tid; i < 512; i += 128) {
            int r = i >> 3, c = i & 7, dsw = r * 8 + (c ^ (r & 7));
            CP16(s2u(&ks4[dsw]), &kg[i]);
            CP16(s2u(&vs4[dsw]), &vg[i]);
        }
        int row = tid >> 1, w = tid & 1;
        CP4(s2u(&mask_s[0][row * 2 + w]), &g_adjbits[(mtile * BM + row) * MASKW + w]);
        CP_COMMIT();
    }

    for (int t = 0; t < NTILES; t++) {
        int buf = t & 1;
        __syncthreads();   // prior compute done before overwriting buf^1
        if (t + 1 < NTILES) {
            int n0 = (t + 1) * BN;
            const uint4* kg = (const uint4*)&g_k[head][n0][0];
            const uint4* vg = (const uint4*)&g_v[head][n0][0];
            uint4* ks4 = (uint4*)k_s[buf ^ 1];
            uint4* vs4 = (uint4*)v_s[buf ^ 1];
            for (int i = tid; i < 512; i += 128) {
                int r = i >> 3, c = i & 7, dsw = r * 8 + (c ^ (r & 7));
                CP16(s2u(&ks4[dsw]), &kg[i]);
                CP16(s2u(&vs4[dsw]), &vg[i]);
            }
            int row = tid >> 1, w = tid & 1;
            CP4(s2u(&mask_s[buf ^ 1][row * 2 + w]),
                &g_adjbits[(mtile * BM + row) * MASKW + (t + 1) * 2 + w]);
            CP_COMMIT();
            CP_WAIT1();
        } else {
            CP_WAIT0();
        }
        __syncthreads();   // tile t fully in smem for all threads

        // ---- S = Q * K^T  (q pre-scaled by 1/8) ----
        float sc[8][4];
        #pragma unroll
        for (int j = 0; j < 8; j++)
            { sc[j][0] = 0.f; sc[j][1] = 0.f; sc[j][2] = 0.f; sc[j][3] = 0.f; }

        char* kb8 = (char*)k_s[buf];
        #pragma unroll
        for (int kt = 0; kt < 4; kt++) {
            uint32_t kb[8][2];
            #pragma unroll
            for (int p = 0; p < 4; p++) {
                int nrow = p * 16 + (lane & 7) + ((lane & 16) ? 8 : 0);
                int kc = kt * 2 + ((lane & 8) ? 1 : 0);
                uint32_t addr = s2u(kb8 + nrow * 128 + ((kc ^ (nrow & 7)) << 4));
                uint32_t r[4]; ldsm4(r, addr);
                kb[2 * p][0] = r[0]; kb[2 * p][1] = r[1];
                kb[2 * p + 1][0] = r[2]; kb[2 * p + 1][1] = r[3];
            }
            #pragma unroll
            for (int j = 0; j < 8; j++) mma16816(sc[j], qf[kt], kb[j]);
        }

        // ---- mask + exp + pack to bf16 A-frags, accumulate row sums ----
        uint32_t mA0 = mask_s[buf][rA * 2], mA1 = mask_s[buf][rA * 2 + 1];
        uint32_t mB0 = mask_s[buf][rB * 2], mB1 = mask_s[buf][rB * 2 + 1];
        uint32_t pa[8][2];
        #pragma unroll
        for (int j = 0; j < 8; j++) {
            int col = j * 8 + t4 * 2;
            uint32_t wA = (j < 4) ? mA0 : mA1;
            uint32_t wB = (j < 4) ? mB0 : mB1;
            int sh = col & 31;
            float e0 = ((wA >> sh) & 1)       ? __expf(sc[j][0]) : 0.f;
            float e1 = ((wA >> (sh + 1)) & 1) ? __expf(sc[j][1]) : 0.f;
            float e2 = ((wB >> sh) & 1)       ? __expf(sc[j][2]) : 0.f;
            float e3 = ((wB >> (sh + 1)) & 1) ? __expf(sc[j][3]) : 0.f;
            lsum0 += e0 + e1;
            lsum1 += e2 + e3;
            __nv_bfloat162 p01 = __floats2bfloat162_rn(e0, e1);
            __nv_bfloat162 p23 = __floats2bfloat162_rn(e2, e3);
            pa[j][0] = *(uint32_t*)&p01;
            pa[j][1] = *(uint32_t*)&p23;
        }

        // ---- O += P * V ----
        char* vb8 = (char*)v_s[buf];
        #pragma unroll
        for (int kt = 0; kt < 4; kt++) {
            uint32_t vb[8][2];
            #pragma unroll
            for (int p = 0; p < 4; p++) {
                int vrow = kt * 16 + (lane & 7) + ((lane & 8) ? 8 : 0);
                int dc = 2 * p + ((lane & 16) ? 1 : 0);
                uint32_t addr = s2u(vb8 + vrow * 128 + ((dc ^ (vrow & 7)) << 4));
                uint32_t r[4]; ldsm4t(r, addr);
                vb[2 * p][0] = r[0]; vb[2 * p][1] = r[1];
                vb[2 * p + 1][0] = r[2]; vb[2 * p + 1][1] = r[3];
            }
            uint32_t a[4] = { pa[2 * kt][0], pa[2 * kt][1],
                              pa[2 * kt + 1][0], pa[2 * kt + 1][1] };
            #pragma unroll
            for (int jd = 0; jd < 8; jd++) mma16816(o[jd], a, vb[jd]);
        }
    }

    // ---- epilogue: normalize, add skip (already resident in out) ----
    lsum0 += __shfl_xor_sync(0xffffffffu, lsum0, 1);
    lsum0 += __shfl_xor_sync(0xffffffffu, lsum0, 2);
    lsum1 += __shfl_xor_sync(0xffffffffu, lsum1, 1);
    lsum1 += __shfl_xor_sync(0xffffffffu, lsum1, 2);
    float inv0 = 1.f / lsum0, inv1 = 1.f / lsum1;

    int nA = mtile * BM + rA;
    int nB = mtile * BM + rB;
    #pragma unroll
    for (int jd = 0; jd < 8; jd++) {
        int d = jd * 8 + t4 * 2;
        long long iA = (long long)nA * 128 + head * 64 + d;
        long long iB = (long long)nB * 128 + head * 64 + d;
        out[iA]     = o[jd][0] * inv0 + out[iA];
        out[iA + 1] = o[jd][1] * inv0 + out[iA + 1];
        out[iB]     = o[jd][2] * inv1 + out[iB];
        out[iB + 1] = o[jd][3] * inv1 + out[iB + 1];
    }
}

// ---------------------------------------------------------------------------
extern "C" void kernel_launch(void* const* d_in, const int* in_sizes, int n_in,
                              void* d_out, int out_size)
{
    const float* h   = (const float*)d_in[0];
    const int*   adj = (const int*)d_in[1];
    const float* Wq  = (const float*)d_in[2];
    const float* bq  = (const float*)d_in[3];
    const float* Wk  = (const float*)d_in[4];
    const float* bk  = (const float*)d_in[5];
    const float* Wv  = (const float*)d_in[6];
    const float* bv  = (const float*)d_in[7];
    const float* Ws  = (const float*)d_in[8];
    const float* bs  = (const float*)d_in[9];
    float* out = (float*)d_out;

    // 1) pack adjacency into bitmask
    pack_adj_kernel<<<(NTOK * (long long)NTOK) / 256, 256>>>(adj);

    // 2) fused projections (writes skip into d_out, Q/K/V to device buffers)
    proj_kernel<<<NTOK / 32, 512>>>(h, Wq, bq, Wk, bk, Wv, bv, Ws, bs, out);

    // 3) masked flash attention, adds on top of skip in d_out
    dim3 grid(NTOK / BM, NHEADS);
    attn_kernel<<<grid, 128>>>(out);
}

// round 6
// speedup vs baseline: 1.1871x; 1.1871x over previous
#include <cuda_runtime.h>
#include <cuda_bf16.h>
#include <cstdint>

#define NTOK   8192
#define INFEAT 128
#define DHEAD  64
#define NHEADS 2
#define MASKW  (NTOK/32)   // 256 words per row

#define BM 64
#define BN 64
#define NTILES (NTOK/BN)   // 128

#define PACK_BLOCKS 4096   // 512 thr each, 1 mask word/thread
#define PROJ_BLOCKS 256    // 32 rows each
// interleave: every 17th block is a proj block -> 4352 total

__device__ __align__(16) uint32_t      g_adjbits[NTOK * MASKW];              // 8 MB
__device__ __align__(16) __nv_bfloat16 g_q[NHEADS][NTOK][DHEAD];             // 2 MB
__device__ __align__(16) __nv_bfloat16 g_k[NHEADS][NTOK][DHEAD];             // 2 MB
__device__ __align__(16) __nv_bfloat16 g_v[NHEADS][NTOK][DHEAD];             // 2 MB

// ---------------------------------------------------------------------------
// Kernel 1: fused prep.
//  - pack blocks: 1 thread = 1 mask word (32 ints via 8x int4, MLP=8)
//  - proj blocks: out[n][f] = sum_k h[n][k]*W[f][k] + b[f]
//    f in [0,512): Q(*0.125,bf16) | K(bf16) | V(bf16) | skip(fp32 -> d_out)
// ---------------------------------------------------------------------------
__global__ void __launch_bounds__(512) prep_kernel(
    const int*   __restrict__ adj,
    const float* __restrict__ h,
    const float* __restrict__ Wq, const float* __restrict__ bq,
    const float* __restrict__ Wk, const float* __restrict__ bk,
    const float* __restrict__ Wv, const float* __restrict__ bv,
    const float* __restrict__ Ws, const float* __restrict__ bs,
    float* __restrict__ out)
{
    __shared__ float4 h_s[32][32];   // only used by proj blocks

    int tid = threadIdx.x;
    int kblk = blockIdx.x / 17;
    int rblk = blockIdx.x % 17;

    if (rblk != 16) {
        // ================= pack branch =================
        int pack_idx = kblk * 16 + rblk;               // 0..4095
        long long g = (long long)pack_idx * 512 + tid; // word index 0..2M-1
        const int4* p = (const int4*)adj + g * 8;      // 32 consecutive ints
        int4 v0 = p[0], v1 = p[1], v2 = p[2], v3 = p[3];
        int4 v4 = p[4], v5 = p[5], v6 = p[6], v7 = p[7];
        uint32_t bits = 0;
        #define PB(v, base) \
            bits |= ((v).x > 0 ? 1u : 0u) << (base);     \
            bits |= ((v).y > 0 ? 1u : 0u) << ((base)+1); \
            bits |= ((v).z > 0 ? 1u : 0u) << ((base)+2); \
            bits |= ((v).w > 0 ? 1u : 0u) << ((base)+3);
        PB(v0, 0)  PB(v1, 4)  PB(v2, 8)  PB(v3, 12)
        PB(v4, 16) PB(v5, 20) PB(v6, 24) PB(v7, 28)
        #undef PB
        g_adjbits[g] = bits;
        return;
    }

    // ================= proj branch =================
    int rowbase = kblk * 32;   // kblk in [0,256)

    const float4* h4 = (const float4*)(h + (long long)rowbase * INFEAT);
    for (int i = tid; i < 32 * 32; i += 512)
        h_s[i >> 5][i & 31] = h4[i];
    __syncthreads();

    int f = tid;
    const float* W; const float* B; int kind, fo;
    if (f < 128)      { W = Wq; B = bq; kind = 0; fo = f; }
    else if (f < 256) { W = Wk; B = bk; kind = 1; fo = f - 128; }
    else if (f < 384) { W = Wv; B = bv; kind = 2; fo = f - 256; }
    else              { W = Ws; B = bs; kind = 3; fo = f - 384; }

    float acc[32];
    float bias = B[fo];
    #pragma unroll
    for (int r = 0; r < 32; r++) acc[r] = bias;

    const float4* Wrow = (const float4*)(W + fo * INFEAT);
    #pragma unroll
    for (int kt = 0; kt < 4; kt++) {
        float4 w[8];
        #pragma unroll
        for (int j = 0; j < 8; j++) w[j] = Wrow[kt * 8 + j];
        #pragma unroll
        for (int r = 0; r < 32; r++) {
            float a = acc[r];
            #pragma unroll
            for (int j = 0; j < 8; j++) {
                float4 hv = h_s[r][kt * 8 + j];
                a += hv.x * w[j].x;
                a += hv.y * w[j].y;
                a += hv.z * w[j].z;
                a += hv.w * w[j].w;
            }
            acc[r] = a;
        }
    }

    int head = fo >> 6, d = fo & 63;
    #pragma unroll
    for (int r = 0; r < 32; r++) {
        int n = rowbase + r;
        if (kind == 0)      g_q[head][n][d] = __float2bfloat16(acc[r] * 0.125f);
        else if (kind == 1) g_k[head][n][d] = __float2bfloat16(acc[r]);
        else if (kind == 2) g_v[head][n][d] = __float2bfloat16(acc[r]);
        else                out[(long long)n * 128 + fo] = acc[r];
    }
}

// ---------------------------------------------------------------------------
// Kernel 2: masked flash attention (no-max softmax), bf16 mma.sync
// ---------------------------------------------------------------------------
__device__ __forceinline__ uint32_t s2u(const void* p) {
    return (uint32_t)__cvta_generic_to_shared(p);
}

#define CP16(dst, src) asm volatile("cp.async.cg.shared.global [%0], [%1], 16;\n" :: "r"(dst), "l"(src) : "memory")
#define CP4(dst, src)  asm volatile("cp.async.ca.shared.global [%0], [%1], 4;\n"  :: "r"(dst), "l"(src) : "memory")
#define CP_COMMIT()    asm volatile("cp.async.commit_group;\n" ::: "memory")
#define CP_WAIT1()     asm volatile("cp.async.wait_group 1;\n" ::: "memory")
#define CP_WAIT0()     asm volatile("cp.async.wait_group 0;\n" ::: "memory")

__device__ __forceinline__ void ldsm4(uint32_t* d, uint32_t addr) {
    asm volatile("ldmatrix.sync.aligned.m8n8.x4.shared.b16 {%0,%1,%2,%3}, [%4];\n"
        : "=r"(d[0]), "=r"(d[1]), "=r"(d[2]), "=r"(d[3]) : "r"(addr));
}
__device__ __forceinline__ void ldsm4t(uint32_t* d, uint32_t addr) {
    asm volatile("ldmatrix.sync.aligned.m8n8.x4.trans.shared.b16 {%0,%1,%2,%3}, [%4];\n"
        : "=r"(d[0]), "=r"(d[1]), "=r"(d[2]), "=r"(d[3]) : "r"(addr));
}
__device__ __forceinline__ void mma16816(float* c, const uint32_t* a, const uint32_t* b) {
    asm volatile("mma.sync.aligned.m16n8k16.row.col.f32.bf16.bf16.f32 "
        "{%0,%1,%2,%3}, {%4,%5,%6,%7}, {%8,%9}, {%0,%1,%2,%3};\n"
        : "+f"(c[0]), "+f"(c[1]), "+f"(c[2]), "+f"(c[3])
        : "r"(a[0]), "r"(a[1]), "r"(a[2]), "r"(a[3]), "r"(b[0]), "r"(b[1]));
}

__global__ void __launch_bounds__(128, 2) attn_kernel(float* __restrict__ out)
{
    int mtile = blockIdx.x, head = blockIdx.y;
    int tid = threadIdx.x, warp = tid >> 5, lane = tid & 31;
    int g = lane >> 2, t4 = lane & 3;

    __shared__ __align__(16) __nv_bfloat16 q_s[BM * DHEAD];        // 8 KB, swizzled
    __shared__ __align__(16) __nv_bfloat16 k_s[2][BN * DHEAD];     // 16 KB
    __shared__ __align__(16) __nv_bfloat16 v_s[2][BN * DHEAD];     // 16 KB
    __shared__ uint32_t mask_s[2][BM * 2];                          // 1 KB

    // ---- stage Q tile (LDG -> STS, swizzled: 16B chunk ^ (row&7)) ----
    {
        const uint4* qg = (const uint4*)&g_q[head][mtile * BM][0];
        uint4* q4 = (uint4*)q_s;
        for (int i = tid; i < 512; i += 128) {
            int r = i >> 3, c = i & 7;
            q4[r * 8 + (c ^ (r & 7))] = qg[i];
        }
    }
    __syncthreads();

    // ---- load Q a-frags into registers (resident whole kernel) ----
    uint32_t qf[4][4];
    {
        char* qb = (char*)q_s;
        #pragma unroll
        for (int kt = 0; kt < 4; kt++) {
            int r = warp * 16 + (lane & 15);
            int kc = kt * 2 + (lane >> 4);
            uint32_t addr = s2u(qb + r * 128 + ((kc ^ (r & 7)) << 4));
            ldsm4(qf[kt], addr);
        }
    }

    float o[8][4];
    #pragma unroll
    for (int j = 0; j < 8; j++)
        { o[j][0] = 0.f; o[j][1] = 0.f; o[j][2] = 0.f; o[j][3] = 0.f; }
    float lsum0 = 0.f, lsum1 = 0.f;

    const int rA = warp * 16 + g, rB = rA + 8;

    // ---- prefetch tile 0 ----
    {
        const uint4* kg = (const uint4*)&g_k[head][0][0];
        const uint4* vg = (const uint4*)&g_v[head][0][0];
        uint4* ks4 = (uint4*)k_s[0];
        uint4* vs4 = (uint4*)v_s[0];
        for (int i = tid; i < 512; i += 128) {
            int r = i >> 3, c = i & 7, dsw = r * 8 + (c ^ (r & 7));
            CP16(s2u(&ks4[dsw]), &kg[i]);
            CP16(s2u(&vs4[dsw]), &vg[i]);
        }
        int row = tid >> 1, w = tid & 1;
        CP4(s2u(&mask_s[0][row * 2 + w]), &g_adjbits[(mtile * BM + row) * MASKW + w]);
        CP_COMMIT();
    }

    for (int t = 0; t < NTILES; t++) {
        int buf = t & 1;
        __syncthreads();   // prior compute done before overwriting buf^1
        if (t + 1 < NTILES) {
            int n0 = (t + 1) * BN;
            const uint4* kg = (const uint4*)&g_k[head][n0][0];
            const uint4* vg = (const uint4*)&g_v[head][n0][0];
            uint4* ks4 = (uint4*)k_s[buf ^ 1];
            uint4* vs4 = (uint4*)v_s[buf ^ 1];
            for (int i = tid; i < 512; i += 128) {
                int r = i >> 3, c = i & 7, dsw = r * 8 + (c ^ (r & 7));
                CP16(s2u(&ks4[dsw]), &kg[i]);
                CP16(s2u(&vs4[dsw]), &vg[i]);
            }
            int row = tid >> 1, w = tid & 1;
            CP4(s2u(&mask_s[buf ^ 1][row * 2 + w]),
                &g_adjbits[(mtile * BM + row) * MASKW + (t + 1) * 2 + w]);
            CP_COMMIT();
            CP_WAIT1();
        } else {
            CP_WAIT0();
        }
        __syncthreads();   // tile t fully in smem for all threads

        // ---- S = Q * K^T  (q pre-scaled by 1/8) ----
        float sc[8][4];
        #pragma unroll
        for (int j = 0; j < 8; j++)
            { sc[j][0] = 0.f; sc[j][1] = 0.f; sc[j][2] = 0.f; sc[j][3] = 0.f; }

        char* kb8 = (char*)k_s[buf];
        #pragma unroll
        for (int kt = 0; kt < 4; kt++) {
            uint32_t kb[8][2];
            #pragma unroll
            for (int p = 0; p < 4; p++) {
                int nrow = p * 16 + (lane & 7) + ((lane & 16) ? 8 : 0);
                int kc = kt * 2 + ((lane & 8) ? 1 : 0);
                uint32_t addr = s2u(kb8 + nrow * 128 + ((kc ^ (nrow & 7)) << 4));
                uint32_t r[4]; ldsm4(r, addr);
                kb[2 * p][0] = r[0]; kb[2 * p][1] = r[1];
                kb[2 * p + 1][0] = r[2]; kb[2 * p + 1][1] = r[3];
            }
            #pragma unroll
            for (int j = 0; j < 8; j++) mma16816(sc[j], qf[kt], kb[j]);
        }

        // ---- mask + exp + pack to bf16 A-frags, accumulate row sums ----
        uint32_t mA0 = mask_s[buf][rA * 2], mA1 = mask_s[buf][rA * 2 + 1];
        uint32_t mB0 = mask_s[buf][rB * 2], mB1 = mask_s[buf][rB * 2 + 1];
        uint32_t pa[8][2];
        #pragma unroll
        for (int j = 0; j < 8; j++) {
            int col = j * 8 + t4 * 2;
            uint32_t wA = (j < 4) ? mA0 : mA1;
            uint32_t wB = (j < 4) ? mB0 : mB1;
            int sh = col & 31;
            float e0 = ((wA >> sh) & 1)       ? __expf(sc[j][0]) : 0.f;
            float e1 = ((wA >> (sh + 1)) & 1) ? __expf(sc[j][1]) : 0.f;
            float e2 = ((wB >> sh) & 1)       ? __expf(sc[j][2]) : 0.f;
            float e3 = ((wB >> (sh + 1)) & 1) ? __expf(sc[j][3]) : 0.f;
            lsum0 += e0 + e1;
            lsum1 += e2 + e3;
            __nv_bfloat162 p01 = __floats2bfloat162_rn(e0, e1);
            __nv_bfloat162 p23 = __floats2bfloat162_rn(e2, e3);
            pa[j][0] = *(uint32_t*)&p01;
            pa[j][1] = *(uint32_t*)&p23;
        }

        // ---- O += P * V ----
        char* vb8 = (char*)v_s[buf];
        #pragma unroll
        for (int kt = 0; kt < 4; kt++) {
            uint32_t vb[8][2];
            #pragma unroll
            for (int p = 0; p < 4; p++) {
                int vrow = kt * 16 + (lane & 7) + ((lane & 8) ? 8 : 0);
                int dc = 2 * p + ((lane & 16) ? 1 : 0);
                uint32_t addr = s2u(vb8 + vrow * 128 + ((dc ^ (vrow & 7)) << 4));
                uint32_t r[4]; ldsm4t(r, addr);
                vb[2 * p][0] = r[0]; vb[2 * p][1] = r[1];
                vb[2 * p + 1][0] = r[2]; vb[2 * p + 1][1] = r[3];
            }
            uint32_t a[4] = { pa[2 * kt][0], pa[2 * kt][1],
                              pa[2 * kt + 1][0], pa[2 * kt + 1][1] };
            #pragma unroll
            for (int jd = 0; jd < 8; jd++) mma16816(o[jd], a, vb[jd]);
        }
    }

    // ---- epilogue: normalize, add skip (already resident in out) ----
    lsum0 += __shfl_xor_sync(0xffffffffu, lsum0, 1);
    lsum0 += __shfl_xor_sync(0xffffffffu, lsum0, 2);
    lsum1 += __shfl_xor_sync(0xffffffffu, lsum1, 1);
    lsum1 += __shfl_xor_sync(0xffffffffu, lsum1, 2);
    float inv0 = 1.f / lsum0, inv1 = 1.f / lsum1;

    int nA = mtile * BM + rA;
    int nB = mtile * BM + rB;
    #pragma unroll
    for (int jd = 0; jd < 8; jd++) {
        int d = jd * 8 + t4 * 2;
        long long iA = (long long)nA * 128 + head * 64 + d;
        long long iB = (long long)nB * 128 + head * 64 + d;
        out[iA]     = o[jd][0] * inv0 + out[iA];
        out[iA + 1] = o[jd][1] * inv0 + out[iA + 1];
        out[iB]     = o[jd][2] * inv1 + out[iB];
        out[iB + 1] = o[jd][3] * inv1 + out[iB + 1];
    }
}

// ---------------------------------------------------------------------------
extern "C" void kernel_launch(void* const* d_in, const int* in_sizes, int n_in,
                              void* d_out, int out_size)
{
    const float* h   = (const float*)d_in[0];
    const int*   adj = (const int*)d_in[1];
    const float* Wq  = (const float*)d_in[2];
    const float* bq  = (const float*)d_in[3];
    const float* Wk  = (const float*)d_in[4];
    const float* bk  = (const float*)d_in[5];
    const float* Wv  = (const float*)d_in[6];
    const float* bv  = (const float*)d_in[7];
    const float* Ws  = (const float*)d_in[8];
    const float* bs  = (const float*)d_in[9];
    float* out = (float*)d_out;

    // 1) fused: pack adjacency bitmask + projections (independent, interleaved)
    prep_kernel<<<PACK_BLOCKS + PROJ_BLOCKS, 512>>>(
        adj, h, Wq, bq, Wk, bk, Wv, bv, Ws, bs, out);

    // 2) masked flash attention, adds on top of skip in d_out
    dim3 grid(NTOK / BM, NHEADS);
    attn_kernel<<<grid, 128>>>(out);
}

// round 7
// speedup vs baseline: 1.2240x; 1.0311x over previous
#include <cuda_runtime.h>
#include <cuda_bf16.h>
#include <cstdint>

#define NTOK   8192
#define INFEAT 128
#define DHEAD  64
#define NHEADS 2
#define MASKW  (NTOK/32)   // 256 words per row

#define BM 64
#define BN 64
#define NTILES (NTOK/BN)   // 128
#define NSPLIT 2
#define TILES_PER_SPLIT (NTILES/NSPLIT)  // 64

#define PACK_BLOCKS 8192   // 512 thr = 16 warps; warp packs 16 words (512 ints)
#define PROJ_BLOCKS 256    // 32 rows each
// interleave: every 33rd block is a proj block -> 33*256 = 8448 total

__device__ __align__(16) uint32_t      g_adjbits[NTOK * MASKW];              // 8 MB
__device__ __align__(16) __nv_bfloat16 g_q[NHEADS][NTOK][DHEAD];             // 2 MB
__device__ __align__(16) __nv_bfloat16 g_k[NHEADS][NTOK][DHEAD];             // 2 MB
__device__ __align__(16) __nv_bfloat16 g_v[NHEADS][NTOK][DHEAD];             // 2 MB
__device__ __align__(16) float         g_opart[NSPLIT][NHEADS][NTOK][DHEAD]; // 8 MB
__device__ __align__(16) float         g_lpart[NSPLIT][NHEADS][NTOK];        // 128 KB

// ---------------------------------------------------------------------------
// Kernel 1: fused prep.
//  - pack blocks: coalesced LDG.32 x16 (MLP=16, nL=1) + 16 ballots/warp
//  - proj blocks: out[n][f] = sum_k h[n][k]*W[f][k] + b[f]
// ---------------------------------------------------------------------------
__global__ void __launch_bounds__(512) prep_kernel(
    const int*   __restrict__ adj,
    const float* __restrict__ h,
    const float* __restrict__ Wq, const float* __restrict__ bq,
    const float* __restrict__ Wk, const float* __restrict__ bk,
    const float* __restrict__ Wv, const float* __restrict__ bv,
    const float* __restrict__ Ws, const float* __restrict__ bs,
    float* __restrict__ out)
{
    __shared__ float4 h_s[32][32];   // only used by proj blocks

    int tid = threadIdx.x;
    int kblk = blockIdx.x / 33;
    int rblk = blockIdx.x % 33;

    if (rblk != 32) {
        // ================= pack branch =================
        int pack_idx = kblk * 32 + rblk;               // 0..8191
        int wlocal = tid >> 5, lane = tid & 31;
        long long W = (long long)pack_idx * 16 + wlocal;  // global warp id
        const int* base = adj + W * 512 + lane;
        int v[16];
        #pragma unroll
        for (int j = 0; j < 16; j++) v[j] = base[j * 32];   // coalesced, MLP=16
        uint32_t myword = 0;
        #pragma unroll
        for (int j = 0; j < 16; j++) {
            uint32_t b = __ballot_sync(0xffffffffu, v[j] > 0);
            if (lane == j) myword = b;
        }
        if (lane < 16)
            g_adjbits[W * 16 + lane] = myword;
        return;
    }

    // ================= proj branch =================
    int rowbase = kblk * 32;   // kblk in [0,256)

    const float4* h4 = (const float4*)(h + (long long)rowbase * INFEAT);
    for (int i = tid; i < 32 * 32; i += 512)
        h_s[i >> 5][i & 31] = h4[i];
    __syncthreads();

    int f = tid;
    const float* Wp; const float* B; int kind, fo;
    if (f < 128)      { Wp = Wq; B = bq; kind = 0; fo = f; }
    else if (f < 256) { Wp = Wk; B = bk; kind = 1; fo = f - 128; }
    else if (f < 384) { Wp = Wv; B = bv; kind = 2; fo = f - 256; }
    else              { Wp = Ws; B = bs; kind = 3; fo = f - 384; }

    float acc[32];
    float bias = B[fo];
    #pragma unroll
    for (int r = 0; r < 32; r++) acc[r] = bias;

    const float4* Wrow = (const float4*)(Wp + fo * INFEAT);
    #pragma unroll
    for (int kt = 0; kt < 4; kt++) {
        float4 w[8];
        #pragma unroll
        for (int j = 0; j < 8; j++) w[j] = Wrow[kt * 8 + j];
        #pragma unroll
        for (int r = 0; r < 32; r++) {
            float a = acc[r];
            #pragma unroll
            for (int j = 0; j < 8; j++) {
                float4 hv = h_s[r][kt * 8 + j];
                a += hv.x * w[j].x;
                a += hv.y * w[j].y;
                a += hv.z * w[j].z;
                a += hv.w * w[j].w;
            }
            acc[r] = a;
        }
    }

    int head = fo >> 6, d = fo & 63;
    #pragma unroll
    for (int r = 0; r < 32; r++) {
        int n = rowbase + r;
        if (kind == 0)      g_q[head][n][d] = __float2bfloat16(acc[r] * 0.125f);
        else if (kind == 1) g_k[head][n][d] = __float2bfloat16(acc[r]);
        else if (kind == 2) g_v[head][n][d] = __float2bfloat16(acc[r]);
        else                out[(long long)n * 128 + fo] = acc[r];
    }
}

// ---------------------------------------------------------------------------
// Kernel 2: masked flash attention (no-max softmax), bf16 mma.sync, split-K x2
// Writes unnormalized partial O + row sums to scratch.
// ---------------------------------------------------------------------------
__device__ __forceinline__ uint32_t s2u(const void* p) {
    return (uint32_t)__cvta_generic_to_shared(p);
}

#define CP16(dst, src) asm volatile("cp.async.cg.shared.global [%0], [%1], 16;\n" :: "r"(dst), "l"(src) : "memory")
#define CP4(dst, src)  asm volatile("cp.async.ca.shared.global [%0], [%1], 4;\n"  :: "r"(dst), "l"(src) : "memory")
#define CP_COMMIT()    asm volatile("cp.async.commit_group;\n" ::: "memory")
#define CP_WAIT1()     asm volatile("cp.async.wait_group 1;\n" ::: "memory")
#define CP_WAIT0()     asm volatile("cp.async.wait_group 0;\n" ::: "memory")

__device__ __forceinline__ void ldsm4(uint32_t* d, uint32_t addr) {
    asm volatile("ldmatrix.sync.aligned.m8n8.x4.shared.b16 {%0,%1,%2,%3}, [%4];\n"
        : "=r"(d[0]), "=r"(d[1]), "=r"(d[2]), "=r"(d[3]) : "r"(addr));
}
__device__ __forceinline__ void ldsm4t(uint32_t* d, uint32_t addr) {
    asm volatile("ldmatrix.sync.aligned.m8n8.x4.trans.shared.b16 {%0,%1,%2,%3}, [%4];\n"
        : "=r"(d[0]), "=r"(d[1]), "=r"(d[2]), "=r"(d[3]) : "r"(addr));
}
__device__ __forceinline__ void mma16816(float* c, const uint32_t* a, const uint32_t* b) {
    asm volatile("mma.sync.aligned.m16n8k16.row.col.f32.bf16.bf16.f32 "
        "{%0,%1,%2,%3}, {%4,%5,%6,%7}, {%8,%9}, {%0,%1,%2,%3};\n"
        : "+f"(c[0]), "+f"(c[1]), "+f"(c[2]), "+f"(c[3])
        : "r"(a[0]), "r"(a[1]), "r"(a[2]), "r"(a[3]), "r"(b[0]), "r"(b[1]));
}

__global__ void __launch_bounds__(128, 3) attn_kernel()
{
    int mtile = blockIdx.x, head = blockIdx.y, split = blockIdx.z;
    int t0 = split * TILES_PER_SPLIT;
    int tid = threadIdx.x, warp = tid >> 5, lane = tid & 31;
    int g = lane >> 2, t4 = lane & 3;

    __shared__ __align__(16) __nv_bfloat16 q_s[BM * DHEAD];        // 8 KB, swizzled
    __shared__ __align__(16) __nv_bfloat16 k_s[2][BN * DHEAD];     // 16 KB
    __shared__ __align__(16) __nv_bfloat16 v_s[2][BN * DHEAD];     // 16 KB
    __shared__ uint32_t mask_s[2][BM * 2];                          // 1 KB

    // ---- stage Q tile (LDG -> STS, swizzled: 16B chunk ^ (row&7)) ----
    {
        const uint4* qg = (const uint4*)&g_q[head][mtile * BM][0];
        uint4* q4 = (uint4*)q_s;
        for (int i = tid; i < 512; i += 128) {
            int r = i >> 3, c = i & 7;
            q4[r * 8 + (c ^ (r & 7))] = qg[i];
        }
    }
    __syncthreads();

    // ---- load Q a-frags into registers (resident whole kernel) ----
    uint32_t qf[4][4];
    {
        char* qb = (char*)q_s;
        #pragma unroll
        for (int kt = 0; kt < 4; kt++) {
            int r = warp * 16 + (lane & 15);
            int kc = kt * 2 + (lane >> 4);
            uint32_t addr = s2u(qb + r * 128 + ((kc ^ (r & 7)) << 4));
            ldsm4(qf[kt], addr);
        }
    }

    float o[8][4];
    #pragma unroll
    for (int j = 0; j < 8; j++)
        { o[j][0] = 0.f; o[j][1] = 0.f; o[j][2] = 0.f; o[j][3] = 0.f; }
    float lsum0 = 0.f, lsum1 = 0.f;

    const int rA = warp * 16 + g, rB = rA + 8;

    // ---- prefetch tile t0 ----
    {
        const uint4* kg = (const uint4*)&g_k[head][t0 * BN][0];
        const uint4* vg = (const uint4*)&g_v[head][t0 * BN][0];
        uint4* ks4 = (uint4*)k_s[0];
        uint4* vs4 = (uint4*)v_s[0];
        for (int i = tid; i < 512; i += 128) {
            int r = i >> 3, c = i & 7, dsw = r * 8 + (c ^ (r & 7));
            CP16(s2u(&ks4[dsw]), &kg[i]);
            CP16(s2u(&vs4[dsw]), &vg[i]);
        }
        int row = tid >> 1, w = tid & 1;
        CP4(s2u(&mask_s[0][row * 2 + w]),
            &g_adjbits[(mtile * BM + row) * MASKW + t0 * 2 + w]);
        CP_COMMIT();
    }

    for (int tt = 0; tt < TILES_PER_SPLIT; tt++) {
        int t = t0 + tt;
        int buf = tt & 1;
        __syncthreads();   // prior compute done before overwriting buf^1
        if (tt + 1 < TILES_PER_SPLIT) {
            int n0 = (t + 1) * BN;
            const uint4* kg = (const uint4*)&g_k[head][n0][0];
            const uint4* vg = (const uint4*)&g_v[head][n0][0];
            uint4* ks4 = (uint4*)k_s[buf ^ 1];
            uint4* vs4 = (uint4*)v_s[buf ^ 1];
            for (int i = tid; i < 512; i += 128) {
                int r = i >> 3, c = i & 7, dsw = r * 8 + (c ^ (r & 7));
                CP16(s2u(&ks4[dsw]), &kg[i]);
                CP16(s2u(&vs4[dsw]), &vg[i]);
            }
            int row = tid >> 1, w = tid & 1;
            CP4(s2u(&mask_s[buf ^ 1][row * 2 + w]),
                &g_adjbits[(mtile * BM + row) * MASKW + (t + 1) * 2 + w]);
            CP_COMMIT();
            CP_WAIT1();
        } else {
            CP_WAIT0();
        }
        __syncthreads();   // tile t fully in smem for all threads

        // ---- S = Q * K^T  (q pre-scaled by 1/8) ----
        float sc[8][4];
        #pragma unroll
        for (int j = 0; j < 8; j++)
            { sc[j][0] = 0.f; sc[j][1] = 0.f; sc[j][2] = 0.f; sc[j][3] = 0.f; }

        char* kb8 = (char*)k_s[buf];
        #pragma unroll
        for (int kt = 0; kt < 4; kt++) {
            uint32_t kb[8][2];
            #pragma unroll
            for (int p = 0; p < 4; p++) {
                int nrow = p * 16 + (lane & 7) + ((lane & 16) ? 8 : 0);
                int kc = kt * 2 + ((lane & 8) ? 1 : 0);
                uint32_t addr = s2u(kb8 + nrow * 128 + ((kc ^ (nrow & 7)) << 4));
                uint32_t r[4]; ldsm4(r, addr);
                kb[2 * p][0] = r[0]; kb[2 * p][1] = r[1];
                kb[2 * p + 1][0] = r[2]; kb[2 * p + 1][1] = r[3];
            }
            #pragma unroll
            for (int j = 0; j < 8; j++) mma16816(sc[j], qf[kt], kb[j]);
        }

        // ---- mask + exp + pack to bf16 A-frags, accumulate row sums ----
        uint32_t mA0 = mask_s[buf][rA * 2], mA1 = mask_s[buf][rA * 2 + 1];
        uint32_t mB0 = mask_s[buf][rB * 2], mB1 = mask_s[buf][rB * 2 + 1];
        uint32_t pa[8][2];
        #pragma unroll
        for (int j = 0; j < 8; j++) {
            int col = j * 8 + t4 * 2;
            uint32_t wA = (j < 4) ? mA0 : mA1;
            uint32_t wB = (j < 4) ? mB0 : mB1;
            int sh = col & 31;
            float e0 = ((wA >> sh) & 1)       ? __expf(sc[j][0]) : 0.f;
            float e1 = ((wA >> (sh + 1)) & 1) ? __expf(sc[j][1]) : 0.f;
            float e2 = ((wB >> sh) & 1)       ? __expf(sc[j][2]) : 0.f;
            float e3 = ((wB >> (sh + 1)) & 1) ? __expf(sc[j][3]) : 0.f;
            lsum0 += e0 + e1;
            lsum1 += e2 + e3;
            __nv_bfloat162 p01 = __floats2bfloat162_rn(e0, e1);
            __nv_bfloat162 p23 = __floats2bfloat162_rn(e2, e3);
            pa[j][0] = *(uint32_t*)&p01;
            pa[j][1] = *(uint32_t*)&p23;
        }

        // ---- O += P * V ----
        char* vb8 = (char*)v_s[buf];
        #pragma unroll
        for (int kt = 0; kt < 4; kt++) {
            uint32_t vb[8][2];
            #pragma unroll
            for (int p = 0; p < 4; p++) {
                int vrow = kt * 16 + (lane & 7) + ((lane & 8) ? 8 : 0);
                int dc = 2 * p + ((lane & 16) ? 1 : 0);
                uint32_t addr = s2u(vb8 + vrow * 128 + ((dc ^ (vrow & 7)) << 4));
                uint32_t r[4]; ldsm4t(r, addr);
                vb[2 * p][0] = r[0]; vb[2 * p][1] = r[1];
                vb[2 * p + 1][0] = r[2]; vb[2 * p + 1][1] = r[3];
            }
            uint32_t a[4] = { pa[2 * kt][0], pa[2 * kt][1],
                              pa[2 * kt + 1][0], pa[2 * kt + 1][1] };
            #pragma unroll
            for (int jd = 0; jd < 8; jd++) mma16816(o[jd], a, vb[jd]);
        }
    }

    // ---- store partial O (unnormalized) + row sums to scratch ----
    lsum0 += __shfl_xor_sync(0xffffffffu, lsum0, 1);
    lsum0 += __shfl_xor_sync(0xffffffffu, lsum0, 2);
    lsum1 += __shfl_xor_sync(0xffffffffu, lsum1, 1);
    lsum1 += __shfl_xor_sync(0xffffffffu, lsum1, 2);

    int nA = mtile * BM + rA;
    int nB = mtile * BM + rB;
    if (t4 == 0) {
        g_lpart[split][head][nA] = lsum0;
        g_lpart[split][head][nB] = lsum1;
    }
    #pragma unroll
    for (int jd = 0; jd < 8; jd++) {
        int d = jd * 8 + t4 * 2;
        *(float2*)&g_opart[split][head][nA][d] = make_float2(o[jd][0], o[jd][1]);
        *(float2*)&g_opart[split][head][nB][d] = make_float2(o[jd][2], o[jd][3]);
    }
}

// ---------------------------------------------------------------------------
// Kernel 3: combine splits, normalize, add skip (already resident in d_out)
// ---------------------------------------------------------------------------
__global__ void __launch_bounds__(256) epilogue_kernel(float* __restrict__ out)
{
    int idx = blockIdx.x * 256 + threadIdx.x;   // float4 index over [8192][128]
    int n = idx >> 5;
    int f4 = idx & 31;
    int head = f4 >> 4;
    int d = (f4 & 15) * 4;
    float4 a = *(const float4*)&g_opart[0][head][n][d];
    float4 b = *(const float4*)&g_opart[1][head][n][d];
    float inv = 1.f / (g_lpart[0][head][n] + g_lpart[1][head][n]);
    float4* po = (float4*)out + idx;
    float4 s = *po;
    s.x += (a.x + b.x) * inv;
    s.y += (a.y + b.y) * inv;
    s.z += (a.z + b.z) * inv;
    s.w += (a.w + b.w) * inv;
    *po = s;
}

// ---------------------------------------------------------------------------
extern "C" void kernel_launch(void* const* d_in, const int* in_sizes, int n_in,
                              void* d_out, int out_size)
{
    const float* h   = (const float*)d_in[0];
    const int*   adj = (const int*)d_in[1];
    const float* Wq  = (const float*)d_in[2];
    const float* bq  = (const float*)d_in[3];
    const float* Wk  = (const float*)d_in[4];
    const float* bk  = (const float*)d_in[5];
    const float* Wv  = (const float*)d_in[6];
    const float* bv  = (const float*)d_in[7];
    const float* Ws  = (const float*)d_in[8];
    const float* bs  = (const float*)d_in[9];
    float* out = (float*)d_out;

    // 1) fused: pack adjacency bitmask (coalesced+ballot) + projections
    prep_kernel<<<33 * 256, 512>>>(
        adj, h, Wq, bq, Wk, bk, Wv, bv, Ws, bs, out);

    // 2) masked flash attention, split-K x2, partials to scratch
    dim3 grid(NTOK / BM, NHEADS, NSPLIT);
    attn_kernel<<<grid, 128>>>();

    // 3) combine + normalize + skip
    epilogue_kernel<<<(NTOK * 128 / 4) / 256, 256>>>(out);
}

// round 8
// speedup vs baseline: 1.5215x; 1.2431x over previous
#include <cuda_runtime.h>
#include <cuda_bf16.h>
#include <cstdint>

#define NTOK   8192
#define INFEAT 128
#define DHEAD  64
#define NHEADS 2
#define MASKW  (NTOK/32)   // 256 words per row

#define BM 64
#define BN 64
#define NTILES (NTOK/BN)   // 128
#define NSPLIT 4
#define TILES_PER_SPLIT (NTILES/NSPLIT)  // 32

__device__ __align__(16) uint32_t      g_adjbits[NTOK * MASKW];              // 8 MB
__device__ __align__(16) __nv_bfloat16 g_q[NHEADS][NTOK][DHEAD];             // 2 MB
__device__ __align__(16) __nv_bfloat16 g_k[NHEADS][NTOK][DHEAD];             // 2 MB
__device__ __align__(16) __nv_bfloat16 g_v[NHEADS][NTOK][DHEAD];             // 2 MB
__device__ __align__(16) float         g_opart[NSPLIT][NHEADS][NTOK][DHEAD]; // 16 MB
__device__ __align__(16) float         g_lpart[NSPLIT][NHEADS][NTOK];        // 256 KB

// ---------------------------------------------------------------------------
// Kernel 1: pack adjacency -> bitmask. Standalone, low-reg, high-occupancy.
// Each warp packs 32 words (1024 ints) via 2 x (16 coalesced LDG.32 + ballot).
// ---------------------------------------------------------------------------
__global__ void __launch_bounds__(256) pack_kernel(const int* __restrict__ adj)
{
    int gwarp = blockIdx.x * 8 + (threadIdx.x >> 5);
    int lane = threadIdx.x & 31;
    long long base = (long long)gwarp * 1024;

    #pragma unroll
    for (int it = 0; it < 2; it++) {
        const int* p = adj + base + it * 512 + lane;
        int v[16];
        #pragma unroll
        for (int j = 0; j < 16; j++) v[j] = p[j * 32];   // MLP=16, 1 line/instr
        uint32_t myword = 0;
        #pragma unroll
        for (int j = 0; j < 16; j++) {
            uint32_t b = __ballot_sync(0xffffffffu, v[j] > 0);
            if (lane == j) myword = b;
        }
        if (lane < 16)
            g_adjbits[gwarp * 32 + it * 16 + lane] = myword;
    }
}

// ---------------------------------------------------------------------------
// Kernel 2: fused projections. out[n][f] = sum_k h[n][k]*W[f][k] + b[f]
// f in [0,512): Q(*0.125,bf16) | K(bf16) | V(bf16) | skip(fp32 -> d_out)
// One block = 32 rows, blockDim = 512 (one thread per feature).
// ---------------------------------------------------------------------------
__global__ void __launch_bounds__(512) proj_kernel(
    const float* __restrict__ h,
    const float* __restrict__ Wq, const float* __restrict__ bq,
    const float* __restrict__ Wk, const float* __restrict__ bk,
    const float* __restrict__ Wv, const float* __restrict__ bv,
    const float* __restrict__ Ws, const float* __restrict__ bs,
    float* __restrict__ out)
{
    __shared__ float4 h_s[32][32];   // 32 rows x 128 floats
    int tid = threadIdx.x;
    int rowbase = blockIdx.x * 32;

    const float4* h4 = (const float4*)(h + (long long)rowbase * INFEAT);
    for (int i = tid; i < 32 * 32; i += 512)
        h_s[i >> 5][i & 31] = h4[i];
    __syncthreads();

    int f = tid;
    const float* W; const float* B; int kind, fo;
    if (f < 128)      { W = Wq; B = bq; kind = 0; fo = f; }
    else if (f < 256) { W = Wk; B = bk; kind = 1; fo = f - 128; }
    else if (f < 384) { W = Wv; B = bv; kind = 2; fo = f - 256; }
    else              { W = Ws; B = bs; kind = 3; fo = f - 384; }

    float acc[32];
    float bias = B[fo];
    #pragma unroll
    for (int r = 0; r < 32; r++) acc[r] = bias;

    const float4* Wrow = (const float4*)(W + fo * INFEAT);
    #pragma unroll
    for (int kt = 0; kt < 4; kt++) {
        float4 w[8];
        #pragma unroll
        for (int j = 0; j < 8; j++) w[j] = Wrow[kt * 8 + j];
        #pragma unroll
        for (int r = 0; r < 32; r++) {
            float a = acc[r];
            #pragma unroll
            for (int j = 0; j < 8; j++) {
                float4 hv = h_s[r][kt * 8 + j];
                a += hv.x * w[j].x;
                a += hv.y * w[j].y;
                a += hv.z * w[j].z;
                a += hv.w * w[j].w;
            }
            acc[r] = a;
        }
    }

    int head = fo >> 6, d = fo & 63;
    #pragma unroll
    for (int r = 0; r < 32; r++) {
        int n = rowbase + r;
        if (kind == 0)      g_q[head][n][d] = __float2bfloat16(acc[r] * 0.125f);
        else if (kind == 1) g_k[head][n][d] = __float2bfloat16(acc[r]);
        else if (kind == 2) g_v[head][n][d] = __float2bfloat16(acc[r]);
        else                out[(long long)n * 128 + fo] = acc[r];
    }
}

// ---------------------------------------------------------------------------
// Kernel 3: masked flash attention (no-max softmax), bf16 mma.sync, split-K x4
// Writes unnormalized partial O + row sums to scratch.
// ---------------------------------------------------------------------------
__device__ __forceinline__ uint32_t s2u(const void* p) {
    return (uint32_t)__cvta_generic_to_shared(p);
}

#define CP16(dst, src) asm volatile("cp.async.cg.shared.global [%0], [%1], 16;\n" :: "r"(dst), "l"(src) : "memory")
#define CP4(dst, src)  asm volatile("cp.async.ca.shared.global [%0], [%1], 4;\n"  :: "r"(dst), "l"(src) : "memory")
#define CP_COMMIT()    asm volatile("cp.async.commit_group;\n" ::: "memory")
#define CP_WAIT1()     asm volatile("cp.async.wait_group 1;\n" ::: "memory")
#define CP_WAIT0()     asm volatile("cp.async.wait_group 0;\n" ::: "memory")

__device__ __forceinline__ void ldsm4(uint32_t* d, uint32_t addr) {
    asm volatile("ldmatrix.sync.aligned.m8n8.x4.shared.b16 {%0,%1,%2,%3}, [%4];\n"
        : "=r"(d[0]), "=r"(d[1]), "=r"(d[2]), "=r"(d[3]) : "r"(addr));
}
__device__ __forceinline__ void ldsm4t(uint32_t* d, uint32_t addr) {
    asm volatile("ldmatrix.sync.aligned.m8n8.x4.trans.shared.b16 {%0,%1,%2,%3}, [%4];\n"
        : "=r"(d[0]), "=r"(d[1]), "=r"(d[2]), "=r"(d[3]) : "r"(addr));
}
__device__ __forceinline__ void mma16816(float* c, const uint32_t* a, const uint32_t* b) {
    asm volatile("mma.sync.aligned.m16n8k16.row.col.f32.bf16.bf16.f32 "
        "{%0,%1,%2,%3}, {%4,%5,%6,%7}, {%8,%9}, {%0,%1,%2,%3};\n"
        : "+f"(c[0]), "+f"(c[1]), "+f"(c[2]), "+f"(c[3])
        : "r"(a[0]), "r"(a[1]), "r"(a[2]), "r"(a[3]), "r"(b[0]), "r"(b[1]));
}

__global__ void __launch_bounds__(128, 3) attn_kernel()
{
    int mtile = blockIdx.x, head = blockIdx.y, split = blockIdx.z;
    int t0 = split * TILES_PER_SPLIT;
    int tid = threadIdx.x, warp = tid >> 5, lane = tid & 31;
    int g = lane >> 2, t4 = lane & 3;

    __shared__ __align__(16) __nv_bfloat16 q_s[BM * DHEAD];        // 8 KB, swizzled
    __shared__ __align__(16) __nv_bfloat16 k_s[2][BN * DHEAD];     // 16 KB
    __shared__ __align__(16) __nv_bfloat16 v_s[2][BN * DHEAD];     // 16 KB
    __shared__ uint32_t mask_s[2][BM * 2];                          // 1 KB

    // ---- stage Q tile (LDG -> STS, swizzled: 16B chunk ^ (row&7)) ----
    {
        const uint4* qg = (const uint4*)&g_q[head][mtile * BM][0];
        uint4* q4 = (uint4*)q_s;
        for (int i = tid; i < 512; i += 128) {
            int r = i >> 3, c = i & 7;
            q4[r * 8 + (c ^ (r & 7))] = qg[i];
        }
    }
    __syncthreads();

    // ---- load Q a-frags into registers (resident whole kernel) ----
    uint32_t qf[4][4];
    {
        char* qb = (char*)q_s;
        #pragma unroll
        for (int kt = 0; kt < 4; kt++) {
            int r = warp * 16 + (lane & 15);
            int kc = kt * 2 + (lane >> 4);
            uint32_t addr = s2u(qb + r * 128 + ((kc ^ (r & 7)) << 4));
            ldsm4(qf[kt], addr);
        }
    }

    float o[8][4];
    #pragma unroll
    for (int j = 0; j < 8; j++)
        { o[j][0] = 0.f; o[j][1] = 0.f; o[j][2] = 0.f; o[j][3] = 0.f; }
    float lsum0 = 0.f, lsum1 = 0.f;

    const int rA = warp * 16 + g, rB = rA + 8;

    // ---- prefetch tile t0 ----
    {
        const uint4* kg = (const uint4*)&g_k[head][t0 * BN][0];
        const uint4* vg = (const uint4*)&g_v[head][t0 * BN][0];
        uint4* ks4 = (uint4*)k_s[0];
        uint4* vs4 = (uint4*)v_s[0];
        for (int i = tid; i < 512; i += 128) {
            int r = i >> 3, c = i & 7, dsw = r * 8 + (c ^ (r & 7));
            CP16(s2u(&ks4[dsw]), &kg[i]);
            CP16(s2u(&vs4[dsw]), &vg[i]);
        }
        int row = tid >> 1, w = tid & 1;
        CP4(s2u(&mask_s[0][row * 2 + w]),
            &g_adjbits[(mtile * BM + row) * MASKW + t0 * 2 + w]);
        CP_COMMIT();
    }

    for (int tt = 0; tt < TILES_PER_SPLIT; tt++) {
        int t = t0 + tt;
        int buf = tt & 1;
        __syncthreads();   // prior compute done before overwriting buf^1
        if (tt + 1 < TILES_PER_SPLIT) {
            int n0 = (t + 1) * BN;
            const uint4* kg = (const uint4*)&g_k[head][n0][0];
            const uint4* vg = (const uint4*)&g_v[head][n0][0];
            uint4* ks4 = (uint4*)k_s[buf ^ 1];
            uint4* vs4 = (uint4*)v_s[buf ^ 1];
            for (int i = tid; i < 512; i += 128) {
                int r = i >> 3, c = i & 7, dsw = r * 8 + (c ^ (r & 7));
                CP16(s2u(&ks4[dsw]), &kg[i]);
                CP16(s2u(&vs4[dsw]), &vg[i]);
            }
            int row = tid >> 1, w = tid & 1;
            CP4(s2u(&mask_s[buf ^ 1][row * 2 + w]),
                &g_adjbits[(mtile * BM + row) * MASKW + (t + 1) * 2 + w]);
            CP_COMMIT();
            CP_WAIT1();
        } else {
            CP_WAIT0();
        }
        __syncthreads();   // tile t fully in smem for all threads

        // ---- S = Q * K^T  (q pre-scaled by 1/8) ----
        float sc[8][4];
        #pragma unroll
        for (int j = 0; j < 8; j++)
            { sc[j][0] = 0.f; sc[j][1] = 0.f; sc[j][2] = 0.f; sc[j][3] = 0.f; }

        char* kb8 = (char*)k_s[buf];
        #pragma unroll
        for (int kt = 0; kt < 4; kt++) {
            uint32_t kb[8][2];
            #pragma unroll
            for (int p = 0; p < 4; p++) {
                int nrow = p * 16 + (lane & 7) + ((lane & 16) ? 8 : 0);
                int kc = kt * 2 + ((lane & 8) ? 1 : 0);
                uint32_t addr = s2u(kb8 + nrow * 128 + ((kc ^ (nrow & 7)) << 4));
                uint32_t r[4]; ldsm4(r, addr);
                kb[2 * p][0] = r[0]; kb[2 * p][1] = r[1];
                kb[2 * p + 1][0] = r[2]; kb[2 * p + 1][1] = r[3];
            }
            #pragma unroll
            for (int j = 0; j < 8; j++) mma16816(sc[j], qf[kt], kb[j]);
        }

        // ---- mask + exp + pack to bf16 A-frags, accumulate row sums ----
        uint32_t mA0 = mask_s[buf][rA * 2], mA1 = mask_s[buf][rA * 2 + 1];
        uint32_t mB0 = mask_s[buf][rB * 2], mB1 = mask_s[buf][rB * 2 + 1];
        uint32_t pa[8][2];
        #pragma unroll
        for (int j = 0; j < 8; j++) {
            int col = j * 8 + t4 * 2;
            uint32_t wA = (j < 4) ? mA0 : mA1;
            uint32_t wB = (j < 4) ? mB0 : mB1;
            int sh = col & 31;
            float e0 = ((wA >> sh) & 1)       ? __expf(sc[j][0]) : 0.f;
            float e1 = ((wA >> (sh + 1)) & 1) ? __expf(sc[j][1]) : 0.f;
            float e2 = ((wB >> sh) & 1)       ? __expf(sc[j][2]) : 0.f;
            float e3 = ((wB >> (sh + 1)) & 1) ? __expf(sc[j][3]) : 0.f;
            lsum0 += e0 + e1;
            lsum1 += e2 + e3;
            __nv_bfloat162 p01 = __floats2bfloat162_rn(e0, e1);
            __nv_bfloat162 p23 = __floats2bfloat162_rn(e2, e3);
            pa[j][0] = *(uint32_t*)&p01;
            pa[j][1] = *(uint32_t*)&p23;
        }

        // ---- O += P * V ----
        char* vb8 = (char*)v_s[buf];
        #pragma unroll
        for (int kt = 0; kt < 4; kt++) {
            uint32_t vb[8][2];
            #pragma unroll
            for (int p = 0; p < 4; p++) {
                int vrow = kt * 16 + (lane & 7) + ((lane & 8) ? 8 : 0);
                int dc = 2 * p + ((lane & 16) ? 1 : 0);
                uint32_t addr = s2u(vb8 + vrow * 128 + ((dc ^ (vrow & 7)) << 4));
                uint32_t r[4]; ldsm4t(r, addr);
                vb[2 * p][0] = r[0]; vb[2 * p][1] = r[1];
                vb[2 * p + 1][0] = r[2]; vb[2 * p + 1][1] = r[3];
            }
            uint32_t a[4] = { pa[2 * kt][0], pa[2 * kt][1],
                              pa[2 * kt + 1][0], pa[2 * kt + 1][1] };
            #pragma unroll
            for (int jd = 0; jd < 8; jd++) mma16816(o[jd], a, vb[jd]);
        }
    }

    // ---- store partial O (unnormalized) + row sums to scratch ----
    lsum0 += __shfl_xor_sync(0xffffffffu, lsum0, 1);
    lsum0 += __shfl_xor_sync(0xffffffffu, lsum0, 2);
    lsum1 += __shfl_xor_sync(0xffffffffu, lsum1, 1);
    lsum1 += __shfl_xor_sync(0xffffffffu, lsum1, 2);

    int nA = mtile * BM + rA;
    int nB = mtile * BM + rB;
    if (t4 == 0) {
        g_lpart[split][head][nA] = lsum0;
        g_lpart[split][head][nB] = lsum1;
    }
    #pragma unroll
    for (int jd = 0; jd < 8; jd++) {
        int d = jd * 8 + t4 * 2;
        *(float2*)&g_opart[split][head][nA][d] = make_float2(o[jd][0], o[jd][1]);
        *(float2*)&g_opart[split][head][nB][d] = make_float2(o[jd][2], o[jd][3]);
    }
}

// ---------------------------------------------------------------------------
// Kernel 4: combine splits, normalize, add skip (already resident in d_out)
// ---------------------------------------------------------------------------
__global__ void __launch_bounds__(256) epilogue_kernel(float* __restrict__ out)
{
    int idx = blockIdx.x * 256 + threadIdx.x;   // float4 index over [8192][128]
    int n = idx >> 5;
    int f4 = idx & 31;
    int head = f4 >> 4;
    int d = (f4 & 15) * 4;

    float4 a = *(const float4*)&g_opart[0][head][n][d];
    float lt = g_lpart[0][head][n];
    #pragma unroll
    for (int s = 1; s < NSPLIT; s++) {
        float4 b = *(const float4*)&g_opart[s][head][n][d];
        a.x += b.x; a.y += b.y; a.z += b.z; a.w += b.w;
        lt += g_lpart[s][head][n];
    }
    float inv = 1.f / lt;
    float4* po = (float4*)out + idx;
    float4 s = *po;
    s.x += a.x * inv;
    s.y += a.y * inv;
    s.z += a.z * inv;
    s.w += a.w * inv;
    *po = s;
}

// ---------------------------------------------------------------------------
extern "C" void kernel_launch(void* const* d_in, const int* in_sizes, int n_in,
                              void* d_out, int out_size)
{
    const float* h   = (const float*)d_in[0];
    const int*   adj = (const int*)d_in[1];
    const float* Wq  = (const float*)d_in[2];
    const float* bq  = (const float*)d_in[3];
    const float* Wk  = (const float*)d_in[4];
    const float* bk  = (const float*)d_in[5];
    const float* Wv  = (const float*)d_in[6];
    const float* bv  = (const float*)d_in[7];
    const float* Ws  = (const float*)d_in[8];
    const float* bs  = (const float*)d_in[9];
    float* out = (float*)d_out;

    // 1) pack adjacency bitmask (high-occupancy, low-reg)
    pack_kernel<<<NTOK * MASKW / (8 * 32), 256>>>(adj);

    // 2) projections (writes skip into d_out, Q/K/V to device buffers)
    proj_kernel<<<NTOK / 32, 512>>>(h, Wq, bq, Wk, bk, Wv, bv, Ws, bs, out);

    // 3) masked flash attention, split-K x4, partials to scratch
    dim3 grid(NTOK / BM, NHEADS, NSPLIT);
    attn_kernel<<<grid, 128>>>();

    // 4) combine + normalize + skip
    epilogue_kernel<<<(NTOK * 128 / 4) / 256, 256>>>(out);
}

// round 9
// speedup vs baseline: 1.5283x; 1.0045x over previous
#include <cuda_runtime.h>
#include <cuda_bf16.h>
#include <cstdint>

#define NTOK   8192
#define INFEAT 128
#define DHEAD  64
#define NHEADS 2
#define MASKW  (NTOK/32)   // 256 words per row

#define BM 64
#define BN 64
#define NTILES (NTOK/BN)   // 128
#define NSPLIT 4
#define TILES_PER_SPLIT (NTILES/NSPLIT)  // 32

__device__ __align__(16) uint32_t      g_adjbits[NTOK * MASKW];              // 8 MB
__device__ __align__(16) __nv_bfloat16 g_q[NHEADS][NTOK][DHEAD];             // 2 MB
__device__ __align__(16) __nv_bfloat16 g_k[NHEADS][NTOK][DHEAD];             // 2 MB
__device__ __align__(16) __nv_bfloat16 g_v[NHEADS][NTOK][DHEAD];             // 2 MB
__device__ __align__(16) float         g_opart[NSPLIT][NHEADS][NTOK][DHEAD]; // 16 MB
__device__ __align__(16) float         g_lpart[NSPLIT][NHEADS][NTOK];        // 256 KB

// ---------------------------------------------------------------------------
// Kernel 1: fused prep, 256 threads/block, low-reg both branches.
//  - pack blocks (8 of 9): warp packs 32 words via 2x(16 coalesced LDG + ballot)
//  - proj blocks (1 of 9): 16 rows x 256 features; acc[16] keeps regs ~75
//    f in [0,512): Q(*0.125,bf16) | K(bf16) | V(bf16) | skip(fp32 -> d_out)
// ---------------------------------------------------------------------------
__global__ void __launch_bounds__(256) prep_kernel(
    const int*   __restrict__ adj,
    const float* __restrict__ h,
    const float* __restrict__ Wq, const float* __restrict__ bq,
    const float* __restrict__ Wk, const float* __restrict__ bk,
    const float* __restrict__ Wv, const float* __restrict__ bv,
    const float* __restrict__ Ws, const float* __restrict__ bs,
    float* __restrict__ out)
{
    __shared__ float4 h_s[16][32];   // 8 KB, proj blocks only

    int tid = threadIdx.x;
    int kblk = blockIdx.x / 9;
    int rblk = blockIdx.x % 9;

    if (rblk != 8) {
        // ================= pack branch =================
        int pack_idx = kblk * 8 + rblk;                  // 0..8191
        int wlocal = tid >> 5, lane = tid & 31;
        long long gwarp = (long long)pack_idx * 8 + wlocal;
        long long base = gwarp * 1024;
        #pragma unroll
        for (int it = 0; it < 2; it++) {
            const int* p = adj + base + it * 512 + lane;
            int v[16];
            #pragma unroll
            for (int j = 0; j < 16; j++) v[j] = p[j * 32];   // MLP=16, 1 line/instr
            uint32_t myword = 0;
            #pragma unroll
            for (int j = 0; j < 16; j++) {
                uint32_t b = __ballot_sync(0xffffffffu, v[j] > 0);
                if (lane == j) myword = b;
            }
            if (lane < 16)
                g_adjbits[gwarp * 32 + it * 16 + lane] = myword;
        }
        return;
    }

    // ================= proj branch =================
    int proj_idx = kblk;                 // 0..1023
    int rowbase = (proj_idx >> 1) * 16;  // 16 rows
    int fhalf = proj_idx & 1;            // feature half

    const float4* h4 = (const float4*)(h + (long long)rowbase * INFEAT);
    for (int i = tid; i < 16 * 32; i += 256)
        h_s[i >> 5][i & 31] = h4[i];
    __syncthreads();

    int f = fhalf * 256 + tid;           // 0..511
    const float* W; const float* B; int kind, fo;
    if (f < 128)      { W = Wq; B = bq; kind = 0; fo = f; }
    else if (f < 256) { W = Wk; B = bk; kind = 1; fo = f - 128; }
    else if (f < 384) { W = Wv; B = bv; kind = 2; fo = f - 256; }
    else              { W = Ws; B = bs; kind = 3; fo = f - 384; }

    float acc[16];
    float bias = B[fo];
    #pragma unroll
    for (int r = 0; r < 16; r++) acc[r] = bias;

    const float4* Wrow = (const float4*)(W + fo * INFEAT);
    #pragma unroll
    for (int kt = 0; kt < 4; kt++) {
        float4 w[8];
        #pragma unroll
        for (int j = 0; j < 8; j++) w[j] = Wrow[kt * 8 + j];
        #pragma unroll
        for (int r = 0; r < 16; r++) {
            float a = acc[r];
            #pragma unroll
            for (int j = 0; j < 8; j++) {
                float4 hv = h_s[r][kt * 8 + j];
                a += hv.x * w[j].x;
                a += hv.y * w[j].y;
                a += hv.z * w[j].z;
                a += hv.w * w[j].w;
            }
            acc[r] = a;
        }
    }

    int head = fo >> 6, d = fo & 63;
    #pragma unroll
    for (int r = 0; r < 16; r++) {
        int n = rowbase + r;
        if (kind == 0)      g_q[head][n][d] = __float2bfloat16(acc[r] * 0.125f);
        else if (kind == 1) g_k[head][n][d] = __float2bfloat16(acc[r]);
        else if (kind == 2) g_v[head][n][d] = __float2bfloat16(acc[r]);
        else                out[(long long)n * 128 + fo] = acc[r];
    }
}

// ---------------------------------------------------------------------------
// Kernel 2: masked flash attention (no-max softmax), bf16 mma.sync, split-K x4
// exp/mask folded into the PV kt-loop (MUFU/HMMA overlap, fewer live regs).
// ---------------------------------------------------------------------------
__device__ __forceinline__ uint32_t s2u(const void* p) {
    return (uint32_t)__cvta_generic_to_shared(p);
}

#define CP16(dst, src) asm volatile("cp.async.cg.shared.global [%0], [%1], 16;\n" :: "r"(dst), "l"(src) : "memory")
#define CP4(dst, src)  asm volatile("cp.async.ca.shared.global [%0], [%1], 4;\n"  :: "r"(dst), "l"(src) : "memory")
#define CP_COMMIT()    asm volatile("cp.async.commit_group;\n" ::: "memory")
#define CP_WAIT1()     asm volatile("cp.async.wait_group 1;\n" ::: "memory")
#define CP_WAIT0()     asm volatile("cp.async.wait_group 0;\n" ::: "memory")

__device__ __forceinline__ void ldsm4(uint32_t* d, uint32_t addr) {
    asm volatile("ldmatrix.sync.aligned.m8n8.x4.shared.b16 {%0,%1,%2,%3}, [%4];\n"
        : "=r"(d[0]), "=r"(d[1]), "=r"(d[2]), "=r"(d[3]) : "r"(addr));
}
__device__ __forceinline__ void ldsm4t(uint32_t* d, uint32_t addr) {
    asm volatile("ldmatrix.sync.aligned.m8n8.x4.trans.shared.b16 {%0,%1,%2,%3}, [%4];\n"
        : "=r"(d[0]), "=r"(d[1]), "=r"(d[2]), "=r"(d[3]) : "r"(addr));
}
__device__ __forceinline__ void mma16816(float* c, const uint32_t* a, const uint32_t* b) {
    asm volatile("mma.sync.aligned.m16n8k16.row.col.f32.bf16.bf16.f32 "
        "{%0,%1,%2,%3}, {%4,%5,%6,%7}, {%8,%9}, {%0,%1,%2,%3};\n"
        : "+f"(c[0]), "+f"(c[1]), "+f"(c[2]), "+f"(c[3])
        : "r"(a[0]), "r"(a[1]), "r"(a[2]), "r"(a[3]), "r"(b[0]), "r"(b[1]));
}

__global__ void __launch_bounds__(128, 3) attn_kernel()
{
    int mtile = blockIdx.x, head = blockIdx.y, split = blockIdx.z;
    int t0 = split * TILES_PER_SPLIT;
    int tid = threadIdx.x, warp = tid >> 5, lane = tid & 31;
    int g = lane >> 2, t4 = lane & 3;

    __shared__ __align__(16) __nv_bfloat16 q_s[BM * DHEAD];        // 8 KB, swizzled
    __shared__ __align__(16) __nv_bfloat16 k_s[2][BN * DHEAD];     // 16 KB
    __shared__ __align__(16) __nv_bfloat16 v_s[2][BN * DHEAD];     // 16 KB
    __shared__ uint32_t mask_s[2][BM * 2];                          // 1 KB

    // ---- stage Q tile (LDG -> STS, swizzled: 16B chunk ^ (row&7)) ----
    {
        const uint4* qg = (const uint4*)&g_q[head][mtile * BM][0];
        uint4* q4 = (uint4*)q_s;
        for (int i = tid; i < 512; i += 128) {
            int r = i >> 3, c = i & 7;
            q4[r * 8 + (c ^ (r & 7))] = qg[i];
        }
    }
    __syncthreads();

    // ---- load Q a-frags into registers (resident whole kernel) ----
    uint32_t qf[4][4];
    {
        char* qb = (char*)q_s;
        #pragma unroll
        for (int kt = 0; kt < 4; kt++) {
            int r = warp * 16 + (lane & 15);
            int kc = kt * 2 + (lane >> 4);
            uint32_t addr = s2u(qb + r * 128 + ((kc ^ (r & 7)) << 4));
            ldsm4(qf[kt], addr);
        }
    }

    float o[8][4];
    #pragma unroll
    for (int j = 0; j < 8; j++)
        { o[j][0] = 0.f; o[j][1] = 0.f; o[j][2] = 0.f; o[j][3] = 0.f; }
    float lsum0 = 0.f, lsum1 = 0.f;

    const int rA = warp * 16 + g, rB = rA + 8;

    // ---- prefetch tile t0 ----
    {
        const uint4* kg = (const uint4*)&g_k[head][t0 * BN][0];
        const uint4* vg = (const uint4*)&g_v[head][t0 * BN][0];
        uint4* ks4 = (uint4*)k_s[0];
        uint4* vs4 = (uint4*)v_s[0];
        for (int i = tid; i < 512; i += 128) {
            int r = i >> 3, c = i & 7, dsw = r * 8 + (c ^ (r & 7));
            CP16(s2u(&ks4[dsw]), &kg[i]);
            CP16(s2u(&vs4[dsw]), &vg[i]);
        }
        int row = tid >> 1, w = tid & 1;
        CP4(s2u(&mask_s[0][row * 2 + w]),
            &g_adjbits[(mtile * BM + row) * MASKW + t0 * 2 + w]);
        CP_COMMIT();
    }

    for (int tt = 0; tt < TILES_PER_SPLIT; tt++) {
        int t = t0 + tt;
        int buf = tt & 1;
        __syncthreads();   // prior compute done before overwriting buf^1
        if (tt + 1 < TILES_PER_SPLIT) {
            int n0 = (t + 1) * BN;
            const uint4* kg = (const uint4*)&g_k[head][n0][0];
            const uint4* vg = (const uint4*)&g_v[head][n0][0];
            uint4* ks4 = (uint4*)k_s[buf ^ 1];
            uint4* vs4 = (uint4*)v_s[buf ^ 1];
            for (int i = tid; i < 512; i += 128) {
                int r = i >> 3, c = i & 7, dsw = r * 8 + (c ^ (r & 7));
                CP16(s2u(&ks4[dsw]), &kg[i]);
                CP16(s2u(&vs4[dsw]), &vg[i]);
            }
            int row = tid >> 1, w = tid & 1;
            CP4(s2u(&mask_s[buf ^ 1][row * 2 + w]),
                &g_adjbits[(mtile * BM + row) * MASKW + (t + 1) * 2 + w]);
            CP_COMMIT();
            CP_WAIT1();
        } else {
            CP_WAIT0();
        }
        __syncthreads();   // tile t fully in smem for all threads

        // ---- S = Q * K^T  (q pre-scaled by 1/8) ----
        float sc[8][4];
        #pragma unroll
        for (int j = 0; j < 8; j++)
            { sc[j][0] = 0.f; sc[j][1] = 0.f; sc[j][2] = 0.f; sc[j][3] = 0.f; }

        char* kb8 = (char*)k_s[buf];
        #pragma unroll
        for (int kt = 0; kt < 4; kt++) {
            uint32_t kb[8][2];
            #pragma unroll
            for (int p = 0; p < 4; p++) {
                int nrow = p * 16 + (lane & 7) + ((lane & 16) ? 8 : 0);
                int kc = kt * 2 + ((lane & 8) ? 1 : 0);
                uint32_t addr = s2u(kb8 + nrow * 128 + ((kc ^ (nrow & 7)) << 4));
                uint32_t r[4]; ldsm4(r, addr);
                kb[2 * p][0] = r[0]; kb[2 * p][1] = r[1];
                kb[2 * p + 1][0] = r[2]; kb[2 * p + 1][1] = r[3];
            }
            #pragma unroll
            for (int j = 0; j < 8; j++) mma16816(sc[j], qf[kt], kb[j]);
        }

        // ---- PV loop with exp/mask folded in per kt ----
        uint32_t mA0 = mask_s[buf][rA * 2], mA1 = mask_s[buf][rA * 2 + 1];
        uint32_t mB0 = mask_s[buf][rB * 2], mB1 = mask_s[buf][rB * 2 + 1];
        char* vb8 = (char*)v_s[buf];
        #pragma unroll
        for (int kt = 0; kt < 4; kt++) {
            // exp/mask/pack for S columns j = 2kt, 2kt+1
            uint32_t a[4];
            #pragma unroll
            for (int jj = 0; jj < 2; jj++) {
                int j = 2 * kt + jj;
                int sh = (j * 8 + t4 * 2) & 31;
                uint32_t wA = (j < 4) ? mA0 : mA1;
                uint32_t wB = (j < 4) ? mB0 : mB1;
                float e0 = ((wA >> sh) & 1)       ? __expf(sc[j][0]) : 0.f;
                float e1 = ((wA >> (sh + 1)) & 1) ? __expf(sc[j][1]) : 0.f;
                float e2 = ((wB >> sh) & 1)       ? __expf(sc[j][2]) : 0.f;
                float e3 = ((wB >> (sh + 1)) & 1) ? __expf(sc[j][3]) : 0.f;
                lsum0 += e0 + e1;
                lsum1 += e2 + e3;
                __nv_bfloat162 p01 = __floats2bfloat162_rn(e0, e1);
                __nv_bfloat162 p23 = __floats2bfloat162_rn(e2, e3);
                a[2 * jj]     = *(uint32_t*)&p01;
                a[2 * jj + 1] = *(uint32_t*)&p23;
            }

            uint32_t vb[8][2];
            #pragma unroll
            for (int p = 0; p < 4; p++) {
                int vrow = kt * 16 + (lane & 7) + ((lane & 8) ? 8 : 0);
                int dc = 2 * p + ((lane & 16) ? 1 : 0);
                uint32_t addr = s2u(vb8 + vrow * 128 + ((dc ^ (vrow & 7)) << 4));
                uint32_t r[4]; ldsm4t(r, addr);
                vb[2 * p][0] = r[0]; vb[2 * p][1] = r[1];
                vb[2 * p + 1][0] = r[2]; vb[2 * p + 1][1] = r[3];
            }
            #pragma unroll
            for (int jd = 0; jd < 8; jd++) mma16816(o[jd], a, vb[jd]);
        }
    }

    // ---- store partial O (unnormalized) + row sums to scratch ----
    lsum0 += __shfl_xor_sync(0xffffffffu, lsum0, 1);
    lsum0 += __shfl_xor_sync(0xffffffffu, lsum0, 2);
    lsum1 += __shfl_xor_sync(0xffffffffu, lsum1, 1);
    lsum1 += __shfl_xor_sync(0xffffffffu, lsum1, 2);

    int nA = mtile * BM + rA;
    int nB = mtile * BM + rB;
    if (t4 == 0) {
        g_lpart[split][head][nA] = lsum0;
        g_lpart[split][head][nB] = lsum1;
    }
    #pragma unroll
    for (int jd = 0; jd < 8; jd++) {
        int d = jd * 8 + t4 * 2;
        *(float2*)&g_opart[split][head][nA][d] = make_float2(o[jd][0], o[jd][1]);
        *(float2*)&g_opart[split][head][nB][d] = make_float2(o[jd][2], o[jd][3]);
    }
}

// ---------------------------------------------------------------------------
// Kernel 3: combine splits, normalize, add skip (already resident in d_out)
// ---------------------------------------------------------------------------
__global__ void __launch_bounds__(256) epilogue_kernel(float* __restrict__ out)
{
    int idx = blockIdx.x * 256 + threadIdx.x;   // float4 index over [8192][128]
    int n = idx >> 5;
    int f4 = idx & 31;
    int head = f4 >> 4;
    int d = (f4 & 15) * 4;

    float4 a = *(const float4*)&g_opart[0][head][n][d];
    float lt = g_lpart[0][head][n];
    #pragma unroll
    for (int s = 1; s < NSPLIT; s++) {
        float4 b = *(const float4*)&g_opart[s][head][n][d];
        a.x += b.x; a.y += b.y; a.z += b.z; a.w += b.w;
        lt += g_lpart[s][head][n];
    }
    float inv = 1.f / lt;
    float4* po = (float4*)out + idx;
    float4 s = *po;
    s.x += a.x * inv;
    s.y += a.y * inv;
    s.z += a.z * inv;
    s.w += a.w * inv;
    *po = s;
}

// ---------------------------------------------------------------------------
extern "C" void kernel_launch(void* const* d_in, const int* in_sizes, int n_in,
                              void* d_out, int out_size)
{
    const float* h   = (const float*)d_in[0];
    const int*   adj = (const int*)d_in[1];
    const float* Wq  = (const float*)d_in[2];
    const float* bq  = (const float*)d_in[3];
    const float* Wk  = (const float*)d_in[4];
    const float* bk  = (const float*)d_in[5];
    const float* Wv  = (const float*)d_in[6];
    const float* bv  = (const float*)d_in[7];
    const float* Ws  = (const float*)d_in[8];
    const float* bs  = (const float*)d_in[9];
    float* out = (float*)d_out;

    // 1) fused prep: pack bitmask + projections (disjoint pipes, interleaved)
    prep_kernel<<<1024 * 9, 256>>>(
        adj, h, Wq, bq, Wk, bk, Wv, bv, Ws, bs, out);

    // 2) masked flash attention, split-K x4, partials to scratch
    dim3 grid(NTOK / BM, NHEADS, NSPLIT);
    attn_kernel<<<grid, 128>>>();

    // 3) combine + normalize + skip
    epilogue_kernel<<<(NTOK * 128 / 4) / 256, 256>>>(out);
}

// round 10
// speedup vs baseline: 1.5593x; 1.0203x over previous
#include <cuda_runtime.h>
#include <cuda_bf16.h>
#include <cstdint>

#define NTOK   8192
#define INFEAT 128
#define DHEAD  64
#define NHEADS 2
#define MASKW  (NTOK/32)   // 256 words per row

#define BM 64
#define BN 64
#define NTILES (NTOK/BN)   // 128
#define NSPLIT 4
#define TILES_PER_SPLIT (NTILES/NSPLIT)  // 32

__device__ __align__(16) uint32_t      g_adjbits[NTOK * MASKW];              // 8 MB
__device__ __align__(16) __nv_bfloat16 g_q[NHEADS][NTOK][DHEAD];             // 2 MB
__device__ __align__(16) __nv_bfloat16 g_k[NHEADS][NTOK][DHEAD];             // 2 MB
__device__ __align__(16) __nv_bfloat16 g_v[NHEADS][NTOK][DHEAD];             // 2 MB
__device__ __align__(16) float         g_opart[NSPLIT][NHEADS][NTOK][DHEAD]; // 16 MB
__device__ __align__(16) float         g_lpart[NSPLIT][NHEADS][NTOK];        // 256 KB

// ---------------------------------------------------------------------------
// Kernel 1: pack adjacency -> bitmask. Standalone, low-reg, high-occupancy.
// Each warp packs 32 words (1024 ints) via 2 x (16 coalesced LDG.32 + ballot).
// ---------------------------------------------------------------------------
__global__ void __launch_bounds__(256) pack_kernel(const int* __restrict__ adj)
{
    int gwarp = blockIdx.x * 8 + (threadIdx.x >> 5);
    int lane = threadIdx.x & 31;
    long long base = (long long)gwarp * 1024;

    #pragma unroll
    for (int it = 0; it < 2; it++) {
        const int* p = adj + base + it * 512 + lane;
        int v[16];
        #pragma unroll
        for (int j = 0; j < 16; j++) v[j] = p[j * 32];   // MLP=16, 1 line/instr
        uint32_t myword = 0;
        #pragma unroll
        for (int j = 0; j < 16; j++) {
            uint32_t b = __ballot_sync(0xffffffffu, v[j] > 0);
            if (lane == j) myword = b;
        }
        if (lane < 16)
            g_adjbits[gwarp * 32 + it * 16 + lane] = myword;
    }
}

// ---------------------------------------------------------------------------
// Kernel 2: slim projections. 256 thr; block = 16 rows x 256 features.
// grid.x = 1024: rowgroup = b>>1, feature half = b&1.
// f in [0,512): Q(*0.125,bf16) | K(bf16) | V(bf16) | skip(fp32 -> d_out)
// ---------------------------------------------------------------------------
__global__ void __launch_bounds__(256) proj_kernel(
    const float* __restrict__ h,
    const float* __restrict__ Wq, const float* __restrict__ bq,
    const float* __restrict__ Wk, const float* __restrict__ bk,
    const float* __restrict__ Wv, const float* __restrict__ bv,
    const float* __restrict__ Ws, const float* __restrict__ bs,
    float* __restrict__ out)
{
    __shared__ float4 h_s[16][32];   // 16 rows x 128 floats = 8 KB
    int tid = threadIdx.x;
    int rowbase = (blockIdx.x >> 1) * 16;
    int fhalf = blockIdx.x & 1;

    const float4* h4 = (const float4*)(h + (long long)rowbase * INFEAT);
    for (int i = tid; i < 16 * 32; i += 256)
        h_s[i >> 5][i & 31] = h4[i];
    __syncthreads();

    int f = fhalf * 256 + tid;           // 0..511
    const float* W; const float* B; int kind, fo;
    if (f < 128)      { W = Wq; B = bq; kind = 0; fo = f; }
    else if (f < 256) { W = Wk; B = bk; kind = 1; fo = f - 128; }
    else if (f < 384) { W = Wv; B = bv; kind = 2; fo = f - 256; }
    else              { W = Ws; B = bs; kind = 3; fo = f - 384; }

    float acc[16];
    float bias = B[fo];
    #pragma unroll
    for (int r = 0; r < 16; r++) acc[r] = bias;

    const float4* Wrow = (const float4*)(W + fo * INFEAT);
    #pragma unroll
    for (int kt = 0; kt < 4; kt++) {
        float4 w[8];
        #pragma unroll
        for (int j = 0; j < 8; j++) w[j] = Wrow[kt * 8 + j];
        #pragma unroll
        for (int r = 0; r < 16; r++) {
            float a = acc[r];
            #pragma unroll
            for (int j = 0; j < 8; j++) {
                float4 hv = h_s[r][kt * 8 + j];
                a += hv.x * w[j].x;
                a += hv.y * w[j].y;
                a += hv.z * w[j].z;
                a += hv.w * w[j].w;
            }
            acc[r] = a;
        }
    }

    int head = fo >> 6, d = fo & 63;
    #pragma unroll
    for (int r = 0; r < 16; r++) {
        int n = rowbase + r;
        if (kind == 0)      g_q[head][n][d] = __float2bfloat16(acc[r] * 0.125f);
        else if (kind == 1) g_k[head][n][d] = __float2bfloat16(acc[r]);
        else if (kind == 2) g_v[head][n][d] = __float2bfloat16(acc[r]);
        else                out[(long long)n * 128 + fo] = acc[r];
    }
}

// ---------------------------------------------------------------------------
// Kernel 3: masked flash attention (no-max softmax), bf16 mma.sync, split-K x4
// occupancy 4 (regs capped at 124), exp/mask folded into the PV kt-loop.
// ---------------------------------------------------------------------------
__device__ __forceinline__ uint32_t s2u(const void* p) {
    return (uint32_t)__cvta_generic_to_shared(p);
}

#define CP16(dst, src) asm volatile("cp.async.cg.shared.global [%0], [%1], 16;\n" :: "r"(dst), "l"(src) : "memory")
#define CP4(dst, src)  asm volatile("cp.async.ca.shared.global [%0], [%1], 4;\n"  :: "r"(dst), "l"(src) : "memory")
#define CP_COMMIT()    asm volatile("cp.async.commit_group;\n" ::: "memory")
#define CP_WAIT1()     asm volatile("cp.async.wait_group 1;\n" ::: "memory")
#define CP_WAIT0()     asm volatile("cp.async.wait_group 0;\n" ::: "memory")

__device__ __forceinline__ void ldsm4(uint32_t* d, uint32_t addr) {
    asm volatile("ldmatrix.sync.aligned.m8n8.x4.shared.b16 {%0,%1,%2,%3}, [%4];\n"
        : "=r"(d[0]), "=r"(d[1]), "=r"(d[2]), "=r"(d[3]) : "r"(addr));
}
__device__ __forceinline__ void ldsm4t(uint32_t* d, uint32_t addr) {
    asm volatile("ldmatrix.sync.aligned.m8n8.x4.trans.shared.b16 {%0,%1,%2,%3}, [%4];\n"
        : "=r"(d[0]), "=r"(d[1]), "=r"(d[2]), "=r"(d[3]) : "r"(addr));
}
__device__ __forceinline__ void mma16816(float* c, const uint32_t* a, const uint32_t* b) {
    asm volatile("mma.sync.aligned.m16n8k16.row.col.f32.bf16.bf16.f32 "
        "{%0,%1,%2,%3}, {%4,%5,%6,%7}, {%8,%9}, {%0,%1,%2,%3};\n"
        : "+f"(c[0]), "+f"(c[1]), "+f"(c[2]), "+f"(c[3])
        : "r"(a[0]), "r"(a[1]), "r"(a[2]), "r"(a[3]), "r"(b[0]), "r"(b[1]));
}

__global__ void __launch_bounds__(128, 4) attn_kernel()
{
    int mtile = blockIdx.x, head = blockIdx.y, split = blockIdx.z;
    int t0 = split * TILES_PER_SPLIT;
    int tid = threadIdx.x, warp = tid >> 5, lane = tid & 31;
    int g = lane >> 2, t4 = lane & 3;

    __shared__ __align__(16) __nv_bfloat16 q_s[BM * DHEAD];        // 8 KB, swizzled
    __shared__ __align__(16) __nv_bfloat16 k_s[2][BN * DHEAD];     // 16 KB
    __shared__ __align__(16) __nv_bfloat16 v_s[2][BN * DHEAD];     // 16 KB
    __shared__ uint32_t mask_s[2][BM * 2];                          // 1 KB

    // ---- stage Q tile (LDG -> STS, swizzled: 16B chunk ^ (row&7)) ----
    {
        const uint4* qg = (const uint4*)&g_q[head][mtile * BM][0];
        uint4* q4 = (uint4*)q_s;
        for (int i = tid; i < 512; i += 128) {
            int r = i >> 3, c = i & 7;
            q4[r * 8 + (c ^ (r & 7))] = qg[i];
        }
    }
    __syncthreads();

    // ---- load Q a-frags into registers (resident whole kernel) ----
    uint32_t qf[4][4];
    {
        char* qb = (char*)q_s;
        #pragma unroll
        for (int kt = 0; kt < 4; kt++) {
            int r = warp * 16 + (lane & 15);
            int kc = kt * 2 + (lane >> 4);
            uint32_t addr = s2u(qb + r * 128 + ((kc ^ (r & 7)) << 4));
            ldsm4(qf[kt], addr);
        }
    }

    float o[8][4];
    #pragma unroll
    for (int j = 0; j < 8; j++)
        { o[j][0] = 0.f; o[j][1] = 0.f; o[j][2] = 0.f; o[j][3] = 0.f; }
    float lsum0 = 0.f, lsum1 = 0.f;

    const int rA = warp * 16 + g, rB = rA + 8;

    // ---- prefetch tile t0 ----
    {
        const uint4* kg = (const uint4*)&g_k[head][t0 * BN][0];
        const uint4* vg = (const uint4*)&g_v[head][t0 * BN][0];
        uint4* ks4 = (uint4*)k_s[0];
        uint4* vs4 = (uint4*)v_s[0];
        for (int i = tid; i < 512; i += 128) {
            int r = i >> 3, c = i & 7, dsw = r * 8 + (c ^ (r & 7));
            CP16(s2u(&ks4[dsw]), &kg[i]);
            CP16(s2u(&vs4[dsw]), &vg[i]);
        }
        int row = tid >> 1, w = tid & 1;
        CP4(s2u(&mask_s[0][row * 2 + w]),
            &g_adjbits[(mtile * BM + row) * MASKW + t0 * 2 + w]);
        CP_COMMIT();
    }

    for (int tt = 0; tt < TILES_PER_SPLIT; tt++) {
        int t = t0 + tt;
        int buf = tt & 1;
        __syncthreads();   // prior compute done before overwriting buf^1
        if (tt + 1 < TILES_PER_SPLIT) {
            int n0 = (t + 1) * BN;
            const uint4* kg = (const uint4*)&g_k[head][n0][0];
            const uint4* vg = (const uint4*)&g_v[head][n0][0];
            uint4* ks4 = (uint4*)k_s[buf ^ 1];
            uint4* vs4 = (uint4*)v_s[buf ^ 1];
            for (int i = tid; i < 512; i += 128) {
                int r = i >> 3, c = i & 7, dsw = r * 8 + (c ^ (r & 7));
                CP16(s2u(&ks4[dsw]), &kg[i]);
                CP16(s2u(&vs4[dsw]), &vg[i]);
            }
            int row = tid >> 1, w = tid & 1;
            CP4(s2u(&mask_s[buf ^ 1][row * 2 + w]),
                &g_adjbits[(mtile * BM + row) * MASKW + (t + 1) * 2 + w]);
            CP_COMMIT();
            CP_WAIT1();
        } else {
            CP_WAIT0();
        }
        __syncthreads();   // tile t fully in smem for all threads

        // ---- S = Q * K^T  (q pre-scaled by 1/8) ----
        float sc[8][4];
        #pragma unroll
        for (int j = 0; j < 8; j++)
            { sc[j][0] = 0.f; sc[j][1] = 0.f; sc[j][2] = 0.f; sc[j][3] = 0.f; }

        char* kb8 = (char*)k_s[buf];
        #pragma unroll
        for (int kt = 0; kt < 4; kt++) {
            uint32_t kb[8][2];
            #pragma unroll
            for (int p = 0; p < 4; p++) {
                int nrow = p * 16 + (lane & 7) + ((lane & 16) ? 8 : 0);
                int kc = kt * 2 + ((lane & 8) ? 1 : 0);
                uint32_t addr = s2u(kb8 + nrow * 128 + ((kc ^ (nrow & 7)) << 4));
                uint32_t r[4]; ldsm4(r, addr);
                kb[2 * p][0] = r[0]; kb[2 * p][1] = r[1];
                kb[2 * p + 1][0] = r[2]; kb[2 * p + 1][1] = r[3];
            }
            #pragma unroll
            for (int j = 0; j < 8; j++) mma16816(sc[j], qf[kt], kb[j]);
        }

        // ---- PV loop with exp/mask folded in per kt ----
        uint32_t mA0 = mask_s[buf][rA * 2], mA1 = mask_s[buf][rA * 2 + 1];
        uint32_t mB0 = mask_s[buf][rB * 2], mB1 = mask_s[buf][rB * 2 + 1];
        char* vb8 = (char*)v_s[buf];
        #pragma unroll
        for (int kt = 0; kt < 4; kt++) {
            // exp/mask/pack for S columns j = 2kt, 2kt+1
            uint32_t a[4];
            #pragma unroll
            for (int jj = 0; jj < 2; jj++) {
                int j = 2 * kt + jj;
                int sh = (j * 8 + t4 * 2) & 31;
                uint32_t wA = (j < 4) ? mA0 : mA1;
                uint32_t wB = (j < 4) ? mB0 : mB1;
                float e0 = ((wA >> sh) & 1)       ? __expf(sc[j][0]) : 0.f;
                float e1 = ((wA >> (sh + 1)) & 1) ? __expf(sc[j][1]) : 0.f;
                float e2 = ((wB >> sh) & 1)       ? __expf(sc[j][2]) : 0.f;
                float e3 = ((wB >> (sh + 1)) & 1) ? __expf(sc[j][3]) : 0.f;
                lsum0 += e0 + e1;
                lsum1 += e2 + e3;
                __nv_bfloat162 p01 = __floats2bfloat162_rn(e0, e1);
                __nv_bfloat162 p23 = __floats2bfloat162_rn(e2, e3);
                a[2 * jj]     = *(uint32_t*)&p01;
                a[2 * jj + 1] = *(uint32_t*)&p23;
            }

            uint32_t vb[8][2];
            #pragma unroll
            for (int p = 0; p < 4; p++) {
                int vrow = kt * 16 + (lane & 7) + ((lane & 8) ? 8 : 0);
                int dc = 2 * p + ((lane & 16) ? 1 : 0);
                uint32_t addr = s2u(vb8 + vrow * 128 + ((dc ^ (vrow & 7)) << 4));
                uint32_t r[4]; ldsm4t(r, addr);
                vb[2 * p][0] = r[0]; vb[2 * p][1] = r[1];
                vb[2 * p + 1][0] = r[2]; vb[2 * p + 1][1] = r[3];
            }
            #pragma unroll
            for (int jd = 0; jd < 8; jd++) mma16816(o[jd], a, vb[jd]);
        }
    }

    // ---- store partial O (unnormalized) + row sums to scratch ----
    lsum0 += __shfl_xor_sync(0xffffffffu, lsum0, 1);
    lsum0 += __shfl_xor_sync(0xffffffffu, lsum0, 2);
    lsum1 += __shfl_xor_sync(0xffffffffu, lsum1, 1);
    lsum1 += __shfl_xor_sync(0xffffffffu, lsum1, 2);

    int nA = mtile * BM + rA;
    int nB = mtile * BM + rB;
    if (t4 == 0) {
        g_lpart[split][head][nA] = lsum0;
        g_lpart[split][head][nB] = lsum1;
    }
    #pragma unroll
    for (int jd = 0; jd < 8; jd++) {
        int d = jd * 8 + t4 * 2;
        *(float2*)&g_opart[split][head][nA][d] = make_float2(o[jd][0], o[jd][1]);
        *(float2*)&g_opart[split][head][nB][d] = make_float2(o[jd][2], o[jd][3]);
    }
}

// ---------------------------------------------------------------------------
// Kernel 4: combine splits, normalize, add skip (already resident in d_out)
// ---------------------------------------------------------------------------
__global__ void __launch_bounds__(256) epilogue_kernel(float* __restrict__ out)
{
    int idx = blockIdx.x * 256 + threadIdx.x;   // float4 index over [8192][128]
    int n = idx >> 5;
    int f4 = idx & 31;
    int head = f4 >> 4;
    int d = (f4 & 15) * 4;

    float4 a = *(const float4*)&g_opart[0][head][n][d];
    float lt = g_lpart[0][head][n];
    #pragma unroll
    for (int s = 1; s < NSPLIT; s++) {
        float4 b = *(const float4*)&g_opart[s][head][n][d];
        a.x += b.x; a.y += b.y; a.z += b.z; a.w += b.w;
        lt += g_lpart[s][head][n];
    }
    float inv = 1.f / lt;
    float4* po = (float4*)out + idx;
    float4 s = *po;
    s.x += a.x * inv;
    s.y += a.y * inv;
    s.z += a.z * inv;
    s.w += a.w * inv;
    *po = s;
}

// ---------------------------------------------------------------------------
extern "C" void kernel_launch(void* const* d_in, const int* in_sizes, int n_in,
                              void* d_out, int out_size)
{
    const float* h   = (const float*)d_in[0];
    const int*   adj = (const int*)d_in[1];
    const float* Wq  = (const float*)d_in[2];
    const float* bq  = (const float*)d_in[3];
    const float* Wk  = (const float*)d_in[4];
    const float* bk  = (const float*)d_in[5];
    const float* Wv  = (const float*)d_in[6];
    const float* bv  = (const float*)d_in[7];
    const float* Ws  = (const float*)d_in[8];
    const float* bs  = (const float*)d_in[9];
    float* out = (float*)d_out;

    // 1) pack adjacency bitmask (high-occupancy, low-reg)
    pack_kernel<<<NTOK * MASKW / (8 * 32), 256>>>(adj);

    // 2) slim projections (writes skip into d_out, Q/K/V to device buffers)
    proj_kernel<<<1024, 256>>>(h, Wq, bq, Wk, bk, Wv, bv, Ws, bs, out);

    // 3) masked flash attention, split-K x4, occ 4, partials to scratch
    dim3 grid(NTOK / BM, NHEADS, NSPLIT);
    attn_kernel<<<grid, 128>>>();

    // 4) combine + normalize + skip
    epilogue_kernel<<<(NTOK * 128 / 4) / 256, 256>>>(out);
}